// round 6
// baseline (speedup 1.0000x reference)
#include <cuda_runtime.h>
#include <math.h>

typedef long long ll;

#define D_    768
#define BSZ   64
#define T_    32
#define NTOK  901
#define NLOC  900
#define DK_   384

// ---------------- scratch (static device globals; no allocation) ----------------
__device__ float g_t1[BSZ * D_];
__device__ float g_u[BSZ * D_];
__device__ float g_t2[BSZ * D_];
__device__ float g_wx[BSZ * 3 * D_];
__device__ float g_wh[BSZ * 3 * D_];
__device__ float g_h[BSZ * D_];
__device__ float g_qemb[BSZ * T_ * D_];
__device__ float g_K[(ll)BSZ * NLOC * D_];
__device__ float g_V[(ll)BSZ * NLOC * D_];
__device__ float g_Q[BSZ * T_ * D_];
__device__ float g_ctx[BSZ * T_ * D_];
__device__ float g_pooled[BSZ * D_];
__device__ float g_hcat[BSZ * 2 * D_];
__device__ float g_x1[BSZ * 1024];
__device__ float g_x2[BSZ * 512];
__device__ float g_scal[2];   // [0] = sum(la_pool), [1] = sum(go_pool)

// ---------------- generic register-blocked SGEMM ----------------
// C[M,N] = accScale * (A @ B(^T)) + biasScale * bias,  optional ReLU.
// A rows can be gathered: row m -> A + (m/rb)*bStride + rOff + (m%rb)*K  (rb>0)
// Requirements: K % BK == 0, N % BN == 0, K % 4 == 0 (float4 loads).
template <int BM, int BN, int BK, int TM, int TN, bool TRANSB, bool RELU>
__global__ void sgemm_k(const float* __restrict__ A, const float* __restrict__ B,
                        const float* __restrict__ bias,
                        const float* __restrict__ accScale,
                        const float* __restrict__ biasScale,
                        float* __restrict__ C, int M, int N, int K, int ldc,
                        int rb, ll bStride, ll rOff)
{
    __shared__ float As[BK][BM];
    __shared__ float Bs[BK][BN];
    const int tid = threadIdx.x;
    const int rowBase = blockIdx.y * BM;
    const int colBase = blockIdx.x * BN;

    const int aRow = tid / (BK / 4);
    const int aCol = (tid % (BK / 4)) * 4;
    const int bRowNT = tid / (BK / 4);
    const int bColNT = (tid % (BK / 4)) * 4;
    const int bRowNN = tid / (BN / 4);
    const int bColNN = (tid % (BN / 4)) * 4;

    const int threadRow = tid / (BN / TN);
    const int threadCol = tid % (BN / TN);

    float acc[TM][TN];
#pragma unroll
    for (int i = 0; i < TM; i++)
#pragma unroll
        for (int j = 0; j < TN; j++) acc[i][j] = 0.f;

    for (int kt = 0; kt < K; kt += BK) {
        // --- load A tile ---
        {
            int gr = rowBase + aRow;
            float4 av = make_float4(0.f, 0.f, 0.f, 0.f);
            if (gr < M) {
                const float* ap;
                if (rb > 0) ap = A + (ll)(gr / rb) * bStride + rOff + (ll)(gr % rb) * K;
                else        ap = A + (ll)gr * K;
                av = *(const float4*)(ap + kt + aCol);
            }
            As[aCol + 0][aRow] = av.x;
            As[aCol + 1][aRow] = av.y;
            As[aCol + 2][aRow] = av.z;
            As[aCol + 3][aRow] = av.w;
        }
        // --- load B tile ---
        if (TRANSB) {
            float4 bv = *(const float4*)(B + (ll)(colBase + bRowNT) * K + kt + bColNT);
            Bs[bColNT + 0][bRowNT] = bv.x;
            Bs[bColNT + 1][bRowNT] = bv.y;
            Bs[bColNT + 2][bRowNT] = bv.z;
            Bs[bColNT + 3][bRowNT] = bv.w;
        } else {
            float4 bv = *(const float4*)(B + (ll)(kt + bRowNN) * N + colBase + bColNN);
            *(float4*)&Bs[bRowNN][bColNN] = bv;
        }
        __syncthreads();

#pragma unroll
        for (int kk = 0; kk < BK; kk++) {
            float ar[TM], br[TN];
#pragma unroll
            for (int i = 0; i < TM; i++) ar[i] = As[kk][threadRow * TM + i];
#pragma unroll
            for (int j = 0; j < TN; j++) br[j] = Bs[kk][threadCol * TN + j];
#pragma unroll
            for (int i = 0; i < TM; i++)
#pragma unroll
                for (int j = 0; j < TN; j++) acc[i][j] += ar[i] * br[j];
        }
        __syncthreads();
    }

    const float asc = accScale ? *accScale : 1.f;
    const float bsc = biasScale ? *biasScale : 1.f;
#pragma unroll
    for (int i = 0; i < TM; i++) {
        int r = rowBase + threadRow * TM + i;
        if (r >= M) continue;
#pragma unroll
        for (int j = 0; j < TN; j++) {
            int c = colBase + threadCol * TN + j;
            float v = asc * acc[i][j] + (bias ? bsc * bias[c] : 0.f);
            if (RELU) v = fmaxf(v, 0.f);
            C[(ll)r * ldc + c] = v;
        }
    }
}

// ---------------- small helpers ----------------
__global__ void pool_sums_k(const float* __restrict__ la_pool, const float* __restrict__ go_pool)
{
    int lane = threadIdx.x;  // 32 threads
    float a = la_pool[lane];
    float b = go_pool[lane];
#pragma unroll
    for (int o = 16; o; o >>= 1) {
        a += __shfl_xor_sync(0xffffffffu, a, o);
        b += __shfl_xor_sync(0xffffffffu, b, o);
    }
    if (lane == 0) { g_scal[0] = a; g_scal[1] = b; }
}

__global__ void gru_gate_k(const float* __restrict__ wx, const float* __restrict__ wh,
                           const float* __restrict__ b_hh, float* __restrict__ h,
                           float* __restrict__ qemb, int t)
{
    int idx = blockIdx.x * blockDim.x + threadIdx.x;
    if (idx >= BSZ * D_) return;
    int b = idx / D_, d = idx % D_;
    ll o = (ll)b * 3 * D_;
    float xr = wx[o + d], xz = wx[o + D_ + d], xn = wx[o + 2 * D_ + d];
    float hr = wh[o + d] + b_hh[d];
    float hz = wh[o + D_ + d] + b_hh[D_ + d];
    float hn = wh[o + 2 * D_ + d] + b_hh[2 * D_ + d];
    float r = 1.f / (1.f + __expf(-(xr + hr)));
    float z = 1.f / (1.f + __expf(-(xz + hz)));
    float n = tanhf(xn + r * hn);
    float hv = (1.f - z) * n + z * h[idx];
    h[idx] = hv;
    qemb[(ll)b * T_ * D_ + (ll)t * D_ + d] = hv;
}

// fused attention for one (batch, head): scores -> softmax -> ctx
__global__ void attn_k(const float* __restrict__ Q, const float* __restrict__ K,
                       const float* __restrict__ V, float* __restrict__ ctx)
{
    const int bh = blockIdx.x;
    const int b = bh >> 1, hh = bh & 1;
    extern __shared__ float sm[];
    float* sQ = sm;                  // 32 rows x 388 (padded)
    float* sS = sm + 32 * 388;       // 32 x 900 scores/attn
    const int tid = threadIdx.x;     // 256

    const float* Qb = Q + (ll)b * T_ * D_ + hh * DK_;
    for (int i = tid; i < T_ * DK_; i += 256) {
        int q = i / DK_, d = i % DK_;
        sQ[q * 388 + d] = Qb[(ll)q * D_ + d];
    }
    __syncthreads();

    const float* Kb = K + (ll)b * NLOC * D_ + hh * DK_;
    const float scale = rsqrtf((float)DK_);
    {
        const int q = tid & 31, kw = tid >> 5;
        const float4* qr = (const float4*)(sQ + q * 388);
        for (int k = kw; k < NLOC; k += 8) {
            const float4* kr = (const float4*)(Kb + (ll)k * D_);
            float s = 0.f;
#pragma unroll 8
            for (int d4 = 0; d4 < DK_ / 4; d4++) {
                float4 a = qr[d4], bb = kr[d4];
                s += a.x * bb.x + a.y * bb.y + a.z * bb.z + a.w * bb.w;
            }
            sS[q * NLOC + k] = s * scale;
        }
    }
    __syncthreads();

    {
        const int lane = tid & 31, wp = tid >> 5;
        for (int q = wp; q < T_; q += 8) {
            float* row = sS + q * NLOC;
            float mx = -1e30f;
            for (int k = lane; k < NLOC; k += 32) mx = fmaxf(mx, row[k]);
#pragma unroll
            for (int o = 16; o; o >>= 1) mx = fmaxf(mx, __shfl_xor_sync(0xffffffffu, mx, o));
            float sum = 0.f;
            for (int k = lane; k < NLOC; k += 32) { float e = __expf(row[k] - mx); row[k] = e; sum += e; }
#pragma unroll
            for (int o = 16; o; o >>= 1) sum += __shfl_xor_sync(0xffffffffu, sum, o);
            float inv = 1.f / sum;
            for (int k = lane; k < NLOC; k += 32) row[k] *= inv;
        }
    }
    __syncthreads();

    const float* Vb = V + (ll)b * NLOC * D_ + hh * DK_;
    float* ctxb = ctx + (ll)b * T_ * D_ + hh * DK_;
    for (int idx = tid; idx < T_ * DK_; idx += 256) {
        int q = idx / DK_, d = idx % DK_;
        const float* arow = sS + q * NLOC;
        float s = 0.f;
#pragma unroll 4
        for (int k = 0; k < NLOC; k++) s += arow[k] * Vb[(ll)k * D_ + d];
        ctxb[(ll)q * D_ + d] = s;
    }
}

__global__ void pool_ctx_k(const float* __restrict__ ctx, const float* __restrict__ la_pool,
                           float* __restrict__ pooled)
{
    int idx = blockIdx.x * blockDim.x + threadIdx.x;
    if (idx >= BSZ * D_) return;
    int b = idx / D_, d = idx % D_;
    float s = 0.f;
#pragma unroll
    for (int t = 0; t < T_; t++) s += la_pool[t] * ctx[(ll)b * T_ * D_ + (ll)t * D_ + d];
    pooled[idx] = s;
}

// ---------------- host-side launch wrappers ----------------
static inline void big_nn(const float* A, const float* B, const float* bias, float* C,
                          int M, int N, int K, int ldc, int rb, ll bStride, ll rOff)
{
    dim3 grid(N / 128, (M + 127) / 128);
    sgemm_k<128, 128, 8, 8, 8, false, false><<<grid, 256>>>(A, B, bias, nullptr, nullptr,
                                                            C, M, N, K, ldc, rb, bStride, rOff);
}
static inline void small_nn(const float* A, const float* B, const float* bias,
                            const float* asc, const float* bsc, float* C,
                            int M, int N, int K, int ldc, int rb, ll bStride, ll rOff,
                            bool relu)
{
    dim3 grid(N / 64, (M + 63) / 64);
    if (relu)
        sgemm_k<64, 64, 16, 4, 4, false, true><<<grid, 256>>>(A, B, bias, asc, bsc, C, M, N, K, ldc, rb, bStride, rOff);
    else
        sgemm_k<64, 64, 16, 4, 4, false, false><<<grid, 256>>>(A, B, bias, asc, bsc, C, M, N, K, ldc, rb, bStride, rOff);
}
static inline void small_nt(const float* A, const float* B, const float* bias,
                            const float* asc, const float* bsc, float* C,
                            int M, int N, int K, int ldc)
{
    dim3 grid(N / 64, (M + 63) / 64);
    sgemm_k<64, 64, 16, 4, 4, true, false><<<grid, 256>>>(A, B, bias, asc, bsc, C, M, N, K, ldc, 0, 0, 0);
}

extern "C" void kernel_launch(void* const* d_in, const int* in_sizes, int n_in,
                              void* d_out, int out_size)
{
    (void)in_sizes; (void)n_in; (void)out_size;
    // input order per metadata: 0 question_embeds (unused!), 1 image_local_embeds,
    // 2 h0, 3 gru_w_ih, 4 gru_w_hh, 5 gru_b_ih, 6 gru_b_hh, 7 ga_w, 8 ga_b, 9 ga_pool,
    // 10 la_w, 11 la_b, 12 la_pool, 13 go_w, 14 go_b, 15 go_pool,
    // 16 f1_w, 17 f1_b, 18 f2_w, 19 f2_b, 20 f3_w, 21 f3_b
    const float* img      = (const float*)d_in[1];
    const float* h0       = (const float*)d_in[2];
    const float* gru_w_ih = (const float*)d_in[3];
    const float* gru_w_hh = (const float*)d_in[4];
    const float* gru_b_ih = (const float*)d_in[5];
    const float* gru_b_hh = (const float*)d_in[6];
    const float* ga_w     = (const float*)d_in[7];
    const float* ga_b     = (const float*)d_in[8];
    const float* ga_pool  = (const float*)d_in[9];
    const float* la_w     = (const float*)d_in[10];
    const float* la_b     = (const float*)d_in[11];
    const float* la_pool  = (const float*)d_in[12];
    const float* go_w     = (const float*)d_in[13];
    const float* go_b     = (const float*)d_in[14];
    const float* go_pool  = (const float*)d_in[15];
    const float* f1_w     = (const float*)d_in[16];
    const float* f1_b     = (const float*)d_in[17];
    const float* f2_w     = (const float*)d_in[18];
    const float* f2_b     = (const float*)d_in[19];
    const float* f3_w     = (const float*)d_in[20];
    const float* f3_b     = (const float*)d_in[21];
    float* out = (float*)d_out;

    float *pt1, *pu, *pt2, *pwx, *pwh, *ph, *pqemb, *pK, *pV, *pQ, *pctx, *ppool, *phcat, *px1, *px2, *pscal;
    cudaGetSymbolAddress((void**)&pt1, g_t1);
    cudaGetSymbolAddress((void**)&pu, g_u);
    cudaGetSymbolAddress((void**)&pt2, g_t2);
    cudaGetSymbolAddress((void**)&pwx, g_wx);
    cudaGetSymbolAddress((void**)&pwh, g_wh);
    cudaGetSymbolAddress((void**)&ph, g_h);
    cudaGetSymbolAddress((void**)&pqemb, g_qemb);
    cudaGetSymbolAddress((void**)&pK, g_K);
    cudaGetSymbolAddress((void**)&pV, g_V);
    cudaGetSymbolAddress((void**)&pQ, g_Q);
    cudaGetSymbolAddress((void**)&pctx, g_ctx);
    cudaGetSymbolAddress((void**)&ppool, g_pooled);
    cudaGetSymbolAddress((void**)&phcat, g_hcat);
    cudaGetSymbolAddress((void**)&px1, g_x1);
    cudaGetSymbolAddress((void**)&px2, g_x2);
    cudaGetSymbolAddress((void**)&pscal, g_scal);

    const ll W2 = (ll)D_ * D_;         // stride between w[i] slabs
    const ll BSTR = (ll)NTOK * D_;     // batch stride inside image_local_embeds

    // pool sums (Σ la_pool, Σ go_pool)
    pool_sums_k<<<1, 32>>>(la_pool, go_pool);

    // ---- ga path (constant GRU input): a = ga_pool0 * ((cls@W2+b2)@W3+b3) ----
    small_nn(img, ga_w + 2 * W2, ga_b + 2 * D_, nullptr, nullptr, pt1, BSZ, D_, D_, D_, 1, BSTR, 0, false);
    small_nn(pt1, ga_w + 3 * W2, ga_b + 3 * D_, nullptr, nullptr, pu, BSZ, D_, D_, D_, 0, 0, 0, false);
    // wx = ga_pool0 * (u @ W_ih^T) + b_ih   (accScale = ga_pool device scalar)
    small_nt(pu, gru_w_ih, gru_b_ih, ga_pool, nullptr, pwx, BSZ, 3 * D_, D_, 3 * D_);

    // ---- go path (constant): hcat[:,768:] = Σgo_pool * ((cls@W2+b2)@W3+b3) ----
    small_nn(img, go_w + 2 * W2, go_b + 2 * D_, nullptr, nullptr, pt2, BSZ, D_, D_, D_, 1, BSTR, 0, false);
    small_nn(pt2, go_w + 3 * W2, go_b + 3 * D_, pscal + 1, pscal + 1, phcat + D_, BSZ, D_, D_, 2 * D_, 0, 0, 0, false);

    // ---- local attention K/V projections over 900 tokens (the big GEMMs) ----
    big_nn(img, la_w + 1 * W2, la_b + 1 * D_, pK, BSZ * NLOC, D_, D_, D_, NLOC, BSTR, D_);
    big_nn(img, la_w + 2 * W2, la_b + 2 * D_, pV, BSZ * NLOC, D_, D_, D_, NLOC, BSTR, D_);

    // ---- GRU (sequential, 32 steps); wx constant, wh recomputed per step ----
    cudaMemcpyAsync(ph, h0, (size_t)BSZ * D_ * sizeof(float), cudaMemcpyDeviceToDevice);
    for (int t = 0; t < T_; t++) {
        small_nt(ph, gru_w_hh, nullptr, nullptr, nullptr, pwh, BSZ, 3 * D_, D_, 3 * D_);
        gru_gate_k<<<(BSZ * D_ + 255) / 256, 256>>>(pwx, pwh, gru_b_hh, ph, pqemb, t);
    }

    // ---- Q projection ----
    big_nn(pqemb, la_w + 0 * W2, la_b + 0 * D_, pQ, BSZ * T_, D_, D_, D_, 0, 0, 0);

    // ---- fused attention (128 blocks = B*NH) ----
    const int attn_smem = (32 * 388 + 32 * NLOC) * 4;  // 164864 bytes
    cudaFuncSetAttribute(attn_k, cudaFuncAttributeMaxDynamicSharedMemorySize, attn_smem);
    attn_k<<<128, 256, attn_smem>>>(pQ, pK, pV, pctx);

    // ---- pool over q then output projection: hcat[:,0:768] ----
    pool_ctx_k<<<(BSZ * D_ + 255) / 256, 256>>>(pctx, la_pool, ppool);
    small_nn(ppool, la_w + 3 * W2, la_b + 3 * D_, nullptr, pscal, phcat, BSZ, D_, D_, 2 * D_, 0, 0, 0, false);

    // ---- MLP head ----
    small_nn(phcat, f1_w, f1_b, nullptr, nullptr, px1, BSZ, 1024, 2 * D_, 1024, 0, 0, 0, false);
    small_nn(px1, f2_w, f2_b, nullptr, nullptr, px2, BSZ, 512, 1024, 512, 0, 0, 0, true);
    small_nn(px2, f3_w, f3_b, nullptr, nullptr, out, BSZ, 1024, 512, 1024, 0, 0, 0, false);
}

// round 7
// speedup vs baseline: 1.2343x; 1.2343x over previous
#include <cuda_runtime.h>
#include <mma.h>
#include <math.h>

using namespace nvcuda;
typedef long long ll;

#define D_    768
#define BSZ   64
#define T_    32
#define NTOK  901
#define NLOC  900
#define DK_   384

// ---------------- scratch (static device globals; no allocation) ----------------
__device__ float g_t1[BSZ * D_];
__device__ float g_u[BSZ * D_];
__device__ float g_t2[BSZ * D_];
__device__ float g_wx[BSZ * 3 * D_];
__device__ float g_h[BSZ * D_];
__device__ float g_h2[BSZ * D_];
__device__ float g_qemb[BSZ * T_ * D_];
__device__ float g_K[(ll)BSZ * NLOC * D_];
__device__ float g_V[(ll)BSZ * NLOC * D_];
__device__ float g_Q[BSZ * T_ * D_];
__device__ float g_ctx[BSZ * T_ * D_];
__device__ float g_pooled[BSZ * D_];
__device__ float g_hcat[BSZ * 2 * D_];
__device__ float g_x1[BSZ * 1024];
__device__ float g_x2[BSZ * 512];
__device__ float g_scal[2];   // [0] = sum(la_pool), [1] = sum(go_pool)

// ================= TF32 tensor-core GEMM =================
// C[M,N] = A@B + bias.  BM=128 BN=128 BK=32, 256 threads = 8 warps (2m x 4n),
// warp tile 64x32 = 4x2 wmma(16x16x8) tiles.  Requires M%128==0, N%128==0, K%32==0.
// A rows gathered: row m -> A + (m/rb)*bStride + rOff + (m%rb)*K (rb>0) else A + m*K.
__global__ void tf32gemm_k(const float* __restrict__ A, const float* __restrict__ B,
                           const float* __restrict__ bias, float* __restrict__ C,
                           int M, int N, int K, int ldc,
                           int rb, ll bStride, ll rOff)
{
    __shared__ float As[128][36];    // [m][k], pad 4
    __shared__ float Bs[32][132];    // [k][n], pad 4
    __shared__ float biasS[16][128];

    const int tid = threadIdx.x;
    const int rowBase = blockIdx.y * 128;
    const int colBase = blockIdx.x * 128;

    const int warpId = tid >> 5;
    const int wm = (warpId >> 2) * 64;   // 0 or 64
    const int wn = (warpId & 3) * 32;    // 0,32,64,96

    // --- stage bias tile (16 identical rows), then init accumulators from it ---
    for (int i = tid; i < 16 * 128; i += 256)
        biasS[i >> 7][i & 127] = bias[colBase + (i & 127)];
    __syncthreads();

    wmma::fragment<wmma::accumulator, 16, 16, 8, float> acc[4][2];
    {
        wmma::fragment<wmma::accumulator, 16, 16, 8, float> bfrag[2];
#pragma unroll
        for (int j = 0; j < 2; j++)
            wmma::load_matrix_sync(bfrag[j], &biasS[0][wn + j * 16], 128, wmma::mem_row_major);
#pragma unroll
        for (int i = 0; i < 4; i++)
#pragma unroll
            for (int j = 0; j < 2; j++)
                acc[i][j] = bfrag[j];
    }
    __syncthreads();

    const int ar  = tid >> 3;          // 0..31
    const int ac4 = (tid & 7) * 4;     // 0..28
    const int br  = tid >> 5;          // 0..7
    const int bc4 = (tid & 31) * 4;    // 0..124

    for (int kt = 0; kt < K; kt += 32) {
        // A tile 128x32 (4 passes of 32 rows), gather + tf32 round
#pragma unroll
        for (int p = 0; p < 4; p++) {
            int row = p * 32 + ar;
            int gr = rowBase + row;
            const float* ap = (rb > 0)
                ? A + (ll)(gr / rb) * bStride + rOff + (ll)(gr % rb) * K
                : A + (ll)gr * K;
            float4 v = *(const float4*)(ap + kt + ac4);
            As[row][ac4 + 0] = wmma::__float_to_tf32(v.x);
            As[row][ac4 + 1] = wmma::__float_to_tf32(v.y);
            As[row][ac4 + 2] = wmma::__float_to_tf32(v.z);
            As[row][ac4 + 3] = wmma::__float_to_tf32(v.w);
        }
        // B tile 32x128 (4 passes of 8 rows)
#pragma unroll
        for (int p = 0; p < 4; p++) {
            int row = p * 8 + br;
            float4 v = *(const float4*)(B + (ll)(kt + row) * N + colBase + bc4);
            Bs[row][bc4 + 0] = wmma::__float_to_tf32(v.x);
            Bs[row][bc4 + 1] = wmma::__float_to_tf32(v.y);
            Bs[row][bc4 + 2] = wmma::__float_to_tf32(v.z);
            Bs[row][bc4 + 3] = wmma::__float_to_tf32(v.w);
        }
        __syncthreads();

#pragma unroll
        for (int ks = 0; ks < 32; ks += 8) {
            wmma::fragment<wmma::matrix_a, 16, 16, 8, wmma::precision::tf32, wmma::row_major> af[4];
            wmma::fragment<wmma::matrix_b, 16, 16, 8, wmma::precision::tf32, wmma::row_major> bf[2];
#pragma unroll
            for (int i = 0; i < 4; i++)
                wmma::load_matrix_sync(af[i], &As[wm + i * 16][ks], 36);
#pragma unroll
            for (int j = 0; j < 2; j++)
                wmma::load_matrix_sync(bf[j], &Bs[ks][wn + j * 16], 132);
#pragma unroll
            for (int i = 0; i < 4; i++)
#pragma unroll
                for (int j = 0; j < 2; j++)
                    wmma::mma_sync(acc[i][j], af[i], bf[j], acc[i][j]);
        }
        __syncthreads();
    }

#pragma unroll
    for (int i = 0; i < 4; i++)
#pragma unroll
        for (int j = 0; j < 2; j++)
            wmma::store_matrix_sync(
                &C[(ll)(rowBase + wm + i * 16) * ldc + colBase + wn + j * 16],
                acc[i][j], ldc, wmma::mem_row_major);
}

// ================= generic register-blocked SGEMM (small shapes) =================
template <int BM, int BN, int BK, int TM, int TN, bool TRANSB, bool RELU>
__global__ void sgemm_k(const float* __restrict__ A, const float* __restrict__ B,
                        const float* __restrict__ bias,
                        const float* __restrict__ accScale,
                        const float* __restrict__ biasScale,
                        float* __restrict__ C, int M, int N, int K, int ldc,
                        int rb, ll bStride, ll rOff)
{
    __shared__ float As[BK][BM];
    __shared__ float Bs[BK][BN];
    const int tid = threadIdx.x;
    const int rowBase = blockIdx.y * BM;
    const int colBase = blockIdx.x * BN;

    const int aRow = tid / (BK / 4);
    const int aCol = (tid % (BK / 4)) * 4;
    const int bRowNT = tid / (BK / 4);
    const int bColNT = (tid % (BK / 4)) * 4;
    const int bRowNN = tid / (BN / 4);
    const int bColNN = (tid % (BN / 4)) * 4;

    const int threadRow = tid / (BN / TN);
    const int threadCol = tid % (BN / TN);

    float acc[TM][TN];
#pragma unroll
    for (int i = 0; i < TM; i++)
#pragma unroll
        for (int j = 0; j < TN; j++) acc[i][j] = 0.f;

    for (int kt = 0; kt < K; kt += BK) {
        {
            int gr = rowBase + aRow;
            float4 av = make_float4(0.f, 0.f, 0.f, 0.f);
            if (gr < M) {
                const float* ap;
                if (rb > 0) ap = A + (ll)(gr / rb) * bStride + rOff + (ll)(gr % rb) * K;
                else        ap = A + (ll)gr * K;
                av = *(const float4*)(ap + kt + aCol);
            }
            As[aCol + 0][aRow] = av.x;
            As[aCol + 1][aRow] = av.y;
            As[aCol + 2][aRow] = av.z;
            As[aCol + 3][aRow] = av.w;
        }
        if (TRANSB) {
            float4 bv = *(const float4*)(B + (ll)(colBase + bRowNT) * K + kt + bColNT);
            Bs[bColNT + 0][bRowNT] = bv.x;
            Bs[bColNT + 1][bRowNT] = bv.y;
            Bs[bColNT + 2][bRowNT] = bv.z;
            Bs[bColNT + 3][bRowNT] = bv.w;
        } else {
            float4 bv = *(const float4*)(B + (ll)(kt + bRowNN) * N + colBase + bColNN);
            *(float4*)&Bs[bRowNN][bColNN] = bv;
        }
        __syncthreads();

#pragma unroll
        for (int kk = 0; kk < BK; kk++) {
            float ar[TM], br[TN];
#pragma unroll
            for (int i = 0; i < TM; i++) ar[i] = As[kk][threadRow * TM + i];
#pragma unroll
            for (int j = 0; j < TN; j++) br[j] = Bs[kk][threadCol * TN + j];
#pragma unroll
            for (int i = 0; i < TM; i++)
#pragma unroll
                for (int j = 0; j < TN; j++) acc[i][j] += ar[i] * br[j];
        }
        __syncthreads();
    }

    const float asc = accScale ? *accScale : 1.f;
    const float bsc = biasScale ? *biasScale : 1.f;
#pragma unroll
    for (int i = 0; i < TM; i++) {
        int r = rowBase + threadRow * TM + i;
        if (r >= M) continue;
#pragma unroll
        for (int j = 0; j < TN; j++) {
            int c = colBase + threadCol * TN + j;
            float v = asc * acc[i][j] + (bias ? bsc * bias[c] : 0.f);
            if (RELU) v = fmaxf(v, 0.f);
            C[(ll)r * ldc + c] = v;
        }
    }
}

// ---------------- small helpers ----------------
__global__ void pool_sums_k(const float* __restrict__ la_pool, const float* __restrict__ go_pool)
{
    int lane = threadIdx.x;
    float a = la_pool[lane];
    float b = go_pool[lane];
#pragma unroll
    for (int o = 16; o; o >>= 1) {
        a += __shfl_xor_sync(0xffffffffu, a, o);
        b += __shfl_xor_sync(0xffffffffu, b, o);
    }
    if (lane == 0) { g_scal[0] = a; g_scal[1] = b; }
}

// ======= fused GRU step: wh slice GEMM + gates, per launch =======
// grid 48: block j handles d in [j*16, j*16+16), all 64 batches, all 3 gates.
// Double-buffered h (hin -> hout) to avoid cross-block read/write race.
__global__ void gru_step_k(const float* __restrict__ wx, const float* __restrict__ Whh,
                           const float* __restrict__ b_hh,
                           const float* __restrict__ hin, float* __restrict__ hout,
                           float* __restrict__ qemb, int t)
{
    __shared__ float hs[32][68];   // [k][b]
    __shared__ float ws[48][33];   // [gate*16+dd][k]
    const int tid = threadIdx.x;   // 256
    const int j = blockIdx.x;
    const int tx = tid & 15;       // d within slice
    const int ty = tid >> 4;       // batch group (4 batches each)

    float accr[4] = {0, 0, 0, 0}, accz[4] = {0, 0, 0, 0}, accn[4] = {0, 0, 0, 0};

    const int hb  = tid >> 3;            // 0..31
    const int hc4 = (tid & 7) * 4;

    for (int kt = 0; kt < D_; kt += 32) {
        // h tile: 64 x 32 -> hs[k][b]
#pragma unroll
        for (int p = 0; p < 2; p++) {
            int bb = p * 32 + hb;
            float4 v = *(const float4*)(hin + (ll)bb * D_ + kt + hc4);
            hs[hc4 + 0][bb] = v.x;
            hs[hc4 + 1][bb] = v.y;
            hs[hc4 + 2][bb] = v.z;
            hs[hc4 + 3][bb] = v.w;
        }
        // W rows: 48 x 32 (rows: gate g, col j*16+dd)
        for (int idx = tid; idx < 384; idx += 256) {
            int r = idx >> 3, c4 = (idx & 7) * 4;
            int g = r >> 4, dd = r & 15;
            ll row = (ll)g * D_ + j * 16 + dd;
            float4 v = *(const float4*)(Whh + row * D_ + kt + c4);
            ws[r][c4 + 0] = v.x;
            ws[r][c4 + 1] = v.y;
            ws[r][c4 + 2] = v.z;
            ws[r][c4 + 3] = v.w;
        }
        __syncthreads();

#pragma unroll
        for (int kk = 0; kk < 32; kk++) {
            float wr = ws[tx][kk], wz = ws[16 + tx][kk], wn = ws[32 + tx][kk];
#pragma unroll
            for (int i = 0; i < 4; i++) {
                float hv = hs[kk][ty * 4 + i];
                accr[i] += hv * wr;
                accz[i] += hv * wz;
                accn[i] += hv * wn;
            }
        }
        __syncthreads();
    }

    const int d = j * 16 + tx;
    const float bhr = b_hh[d], bhz = b_hh[D_ + d], bhn = b_hh[2 * D_ + d];
#pragma unroll
    for (int i = 0; i < 4; i++) {
        int b = ty * 4 + i;
        ll o = (ll)b * 3 * D_;
        float xr = wx[o + d], xz = wx[o + D_ + d], xn = wx[o + 2 * D_ + d];
        float r = 1.f / (1.f + __expf(-(xr + accr[i] + bhr)));
        float z = 1.f / (1.f + __expf(-(xz + accz[i] + bhz)));
        float n = tanhf(xn + r * (accn[i] + bhn));
        float hv = (1.f - z) * n + z * hin[(ll)b * D_ + d];
        hout[(ll)b * D_ + d] = hv;
        qemb[(ll)b * T_ * D_ + (ll)t * D_ + d] = hv;
    }
}

// fused attention for one (batch, head): scores -> softmax -> ctx
__global__ void attn_k(const float* __restrict__ Q, const float* __restrict__ K,
                       const float* __restrict__ V, float* __restrict__ ctx)
{
    const int bh = blockIdx.x;
    const int b = bh >> 1, hh = bh & 1;
    extern __shared__ float sm[];
    float* sQ = sm;                  // 32 rows x 388 (padded)
    float* sS = sm + 32 * 388;       // 32 x 900 scores/attn
    const int tid = threadIdx.x;     // 256

    const float* Qb = Q + (ll)b * T_ * D_ + hh * DK_;
    for (int i = tid; i < T_ * DK_; i += 256) {
        int q = i / DK_, d = i % DK_;
        sQ[q * 388 + d] = Qb[(ll)q * D_ + d];
    }
    __syncthreads();

    const float* Kb = K + (ll)b * NLOC * D_ + hh * DK_;
    const float scale = rsqrtf((float)DK_);
    {
        const int q = tid & 31, kw = tid >> 5;
        const float4* qr = (const float4*)(sQ + q * 388);
        for (int k = kw; k < NLOC; k += 8) {
            const float4* kr = (const float4*)(Kb + (ll)k * D_);
            float s = 0.f;
#pragma unroll 8
            for (int d4 = 0; d4 < DK_ / 4; d4++) {
                float4 a = qr[d4], bb = kr[d4];
                s += a.x * bb.x + a.y * bb.y + a.z * bb.z + a.w * bb.w;
            }
            sS[q * NLOC + k] = s * scale;
        }
    }
    __syncthreads();

    {
        const int lane = tid & 31, wp = tid >> 5;
        for (int q = wp; q < T_; q += 8) {
            float* row = sS + q * NLOC;
            float mx = -1e30f;
            for (int k = lane; k < NLOC; k += 32) mx = fmaxf(mx, row[k]);
#pragma unroll
            for (int o = 16; o; o >>= 1) mx = fmaxf(mx, __shfl_xor_sync(0xffffffffu, mx, o));
            float sum = 0.f;
            for (int k = lane; k < NLOC; k += 32) { float e = __expf(row[k] - mx); row[k] = e; sum += e; }
#pragma unroll
            for (int o = 16; o; o >>= 1) sum += __shfl_xor_sync(0xffffffffu, sum, o);
            float inv = 1.f / sum;
            for (int k = lane; k < NLOC; k += 32) row[k] *= inv;
        }
    }
    __syncthreads();

    const float* Vb = V + (ll)b * NLOC * D_ + hh * DK_;
    float* ctxb = ctx + (ll)b * T_ * D_ + hh * DK_;
    for (int idx = tid; idx < T_ * DK_; idx += 256) {
        int q = idx / DK_, d = idx % DK_;
        const float* arow = sS + q * NLOC;
        const float* vp = Vb + d;
        float s0 = 0.f, s1 = 0.f, s2 = 0.f, s3 = 0.f;
        for (int k = 0; k < NLOC; k += 4) {
            s0 += arow[k + 0] * vp[(ll)(k + 0) * D_];
            s1 += arow[k + 1] * vp[(ll)(k + 1) * D_];
            s2 += arow[k + 2] * vp[(ll)(k + 2) * D_];
            s3 += arow[k + 3] * vp[(ll)(k + 3) * D_];
        }
        ctxb[(ll)q * D_ + d] = (s0 + s1) + (s2 + s3);
    }
}

__global__ void pool_ctx_k(const float* __restrict__ ctx, const float* __restrict__ la_pool,
                           float* __restrict__ pooled)
{
    int idx = blockIdx.x * blockDim.x + threadIdx.x;
    if (idx >= BSZ * D_) return;
    int b = idx / D_, d = idx % D_;
    float s = 0.f;
#pragma unroll
    for (int t = 0; t < T_; t++) s += la_pool[t] * ctx[(ll)b * T_ * D_ + (ll)t * D_ + d];
    pooled[idx] = s;
}

// ---------------- host-side launch wrappers ----------------
static inline void big_tc(const float* A, const float* B, const float* bias, float* C,
                          int M, int N, int K, int ldc, int rb, ll bStride, ll rOff)
{
    dim3 grid(N / 128, M / 128);
    tf32gemm_k<<<grid, 256>>>(A, B, bias, C, M, N, K, ldc, rb, bStride, rOff);
}
static inline void small_nn(const float* A, const float* B, const float* bias,
                            const float* asc, const float* bsc, float* C,
                            int M, int N, int K, int ldc, int rb, ll bStride, ll rOff,
                            bool relu)
{
    dim3 grid(N / 64, (M + 63) / 64);
    if (relu)
        sgemm_k<64, 64, 16, 4, 4, false, true><<<grid, 256>>>(A, B, bias, asc, bsc, C, M, N, K, ldc, rb, bStride, rOff);
    else
        sgemm_k<64, 64, 16, 4, 4, false, false><<<grid, 256>>>(A, B, bias, asc, bsc, C, M, N, K, ldc, rb, bStride, rOff);
}
static inline void small_nt(const float* A, const float* B, const float* bias,
                            const float* asc, const float* bsc, float* C,
                            int M, int N, int K, int ldc)
{
    dim3 grid(N / 64, (M + 63) / 64);
    sgemm_k<64, 64, 16, 4, 4, true, false><<<grid, 256>>>(A, B, bias, asc, bsc, C, M, N, K, ldc, 0, 0, 0);
}

extern "C" void kernel_launch(void* const* d_in, const int* in_sizes, int n_in,
                              void* d_out, int out_size)
{
    (void)in_sizes; (void)n_in; (void)out_size;
    const float* img      = (const float*)d_in[1];
    const float* h0       = (const float*)d_in[2];
    const float* gru_w_ih = (const float*)d_in[3];
    const float* gru_w_hh = (const float*)d_in[4];
    const float* gru_b_hh = (const float*)d_in[6];
    const float* gru_b_ih = (const float*)d_in[5];
    const float* ga_w     = (const float*)d_in[7];
    const float* ga_b     = (const float*)d_in[8];
    const float* ga_pool  = (const float*)d_in[9];
    const float* la_w     = (const float*)d_in[10];
    const float* la_b     = (const float*)d_in[11];
    const float* la_pool  = (const float*)d_in[12];
    const float* go_w     = (const float*)d_in[13];
    const float* go_b     = (const float*)d_in[14];
    const float* go_pool  = (const float*)d_in[15];
    const float* f1_w     = (const float*)d_in[16];
    const float* f1_b     = (const float*)d_in[17];
    const float* f2_w     = (const float*)d_in[18];
    const float* f2_b     = (const float*)d_in[19];
    const float* f3_w     = (const float*)d_in[20];
    const float* f3_b     = (const float*)d_in[21];
    float* out = (float*)d_out;

    float *pt1, *pu, *pt2, *pwx, *ph, *ph2, *pqemb, *pK, *pV, *pQ, *pctx, *ppool, *phcat, *px1, *px2, *pscal;
    cudaGetSymbolAddress((void**)&pt1, g_t1);
    cudaGetSymbolAddress((void**)&pu, g_u);
    cudaGetSymbolAddress((void**)&pt2, g_t2);
    cudaGetSymbolAddress((void**)&pwx, g_wx);
    cudaGetSymbolAddress((void**)&ph, g_h);
    cudaGetSymbolAddress((void**)&ph2, g_h2);
    cudaGetSymbolAddress((void**)&pqemb, g_qemb);
    cudaGetSymbolAddress((void**)&pK, g_K);
    cudaGetSymbolAddress((void**)&pV, g_V);
    cudaGetSymbolAddress((void**)&pQ, g_Q);
    cudaGetSymbolAddress((void**)&pctx, g_ctx);
    cudaGetSymbolAddress((void**)&ppool, g_pooled);
    cudaGetSymbolAddress((void**)&phcat, g_hcat);
    cudaGetSymbolAddress((void**)&px1, g_x1);
    cudaGetSymbolAddress((void**)&px2, g_x2);
    cudaGetSymbolAddress((void**)&pscal, g_scal);

    const ll W2 = (ll)D_ * D_;
    const ll BSTR = (ll)NTOK * D_;

    pool_sums_k<<<1, 32>>>(la_pool, go_pool);

    // ---- ga path (constant GRU input): wx = ga_pool0*(((cls@W2+b2)@W3+b3)@W_ih^T) + b_ih ----
    small_nn(img, ga_w + 2 * W2, ga_b + 2 * D_, nullptr, nullptr, pt1, BSZ, D_, D_, D_, 1, BSTR, 0, false);
    small_nn(pt1, ga_w + 3 * W2, ga_b + 3 * D_, nullptr, nullptr, pu, BSZ, D_, D_, D_, 0, 0, 0, false);
    small_nt(pu, gru_w_ih, gru_b_ih, ga_pool, nullptr, pwx, BSZ, 3 * D_, D_, 3 * D_);

    // ---- go path (constant): hcat[:,768:] = sum(go_pool) * ((cls@W2+b2)@W3+b3) ----
    small_nn(img, go_w + 2 * W2, go_b + 2 * D_, nullptr, nullptr, pt2, BSZ, D_, D_, D_, 1, BSTR, 0, false);
    small_nn(pt2, go_w + 3 * W2, go_b + 3 * D_, pscal + 1, pscal + 1, phcat + D_, BSZ, D_, D_, 2 * D_, 0, 0, 0, false);

    // ---- local attention K/V projections over 900 tokens (tf32 tensor cores) ----
    big_tc(img, la_w + 1 * W2, la_b + 1 * D_, pK, BSZ * NLOC, D_, D_, D_, NLOC, BSTR, D_);
    big_tc(img, la_w + 2 * W2, la_b + 2 * D_, pV, BSZ * NLOC, D_, D_, D_, NLOC, BSTR, D_);

    // ---- GRU: 32 fused steps, double-buffered h ----
    cudaMemcpyAsync(ph, h0, (size_t)BSZ * D_ * sizeof(float), cudaMemcpyDeviceToDevice);
    for (int t = 0; t < T_; t++) {
        const float* hin = (t & 1) ? ph2 : ph;
        float* hout      = (t & 1) ? ph  : ph2;
        gru_step_k<<<48, 256>>>(pwx, gru_w_hh, gru_b_hh, hin, hout, pqemb, t);
    }

    // ---- Q projection (tf32 tensor cores) ----
    big_tc(pqemb, la_w + 0 * W2, la_b + 0 * D_, pQ, BSZ * T_, D_, D_, D_, 0, 0, 0);

    // ---- fused attention (128 blocks = B*NH) ----
    const int attn_smem = (32 * 388 + 32 * NLOC) * 4;
    cudaFuncSetAttribute(attn_k, cudaFuncAttributeMaxDynamicSharedMemorySize, attn_smem);
    attn_k<<<128, 256, attn_smem>>>(pQ, pK, pV, pctx);

    // ---- pool over q then output projection: hcat[:,0:768] ----
    pool_ctx_k<<<(BSZ * D_ + 255) / 256, 256>>>(pctx, la_pool, ppool);
    small_nn(ppool, la_w + 3 * W2, la_b + 3 * D_, nullptr, pscal, phcat, BSZ, D_, D_, 2 * D_, 0, 0, 0, false);

    // ---- MLP head ----
    small_nn(phcat, f1_w, f1_b, nullptr, nullptr, px1, BSZ, 1024, 2 * D_, 1024, 0, 0, 0, false);
    small_nn(px1, f2_w, f2_b, nullptr, nullptr, px2, BSZ, 512, 1024, 512, 0, 0, 0, true);
    small_nn(px2, f3_w, f3_b, nullptr, nullptr, out, BSZ, 1024, 512, 1024, 0, 0, 0, false);
}

// round 9
// speedup vs baseline: 5.2092x; 4.2202x over previous
#include <cuda_runtime.h>
#include <mma.h>
#include <math.h>

using namespace nvcuda;
typedef long long ll;

#define D_    768
#define BSZ   64
#define T_    32
#define NTOK  901
#define NLOC  900
#define DK_   384
#define M_Q   (BSZ * T_)   // 2048

// ---------------- scratch (static device globals; no allocation) ----------------
__device__ float g_t1[BSZ * D_];
__device__ float g_u[BSZ * D_];
__device__ float g_t2[BSZ * D_];
__device__ float g_wx[BSZ * 3 * D_];
__device__ float g_h[BSZ * D_];
__device__ float g_h2[BSZ * D_];
__device__ float g_qemb[M_Q * D_];
__device__ float g_Q[M_Q * D_];
__device__ float g_Qt[2 * M_Q * D_];          // per-head query-side K-projection
__device__ float g_qb[2 * M_Q];               // Q_h . bk_h
__device__ float g_S[(ll)BSZ * 2 * T_ * NLOC];// scores/attn [bh][q][900]
__device__ float g_wk[BSZ * 2 * NLOC];        // pooled attention weights
__device__ float g_pctxi[BSZ * 2 * D_];       // pooled attn@img  [bh][768]
__device__ float g_pooled[BSZ * D_];
__device__ float g_hcat[BSZ * 2 * D_];
__device__ float g_x1[BSZ * 1024];
__device__ float g_x2[BSZ * 512];
__device__ float g_scal[2];   // [0] = sum(la_pool), [1] = sum(go_pool)

// ================= TF32 tensor-core GEMM (Q projection) =================
__global__ void tf32gemm_k(const float* __restrict__ A, const float* __restrict__ B,
                           const float* __restrict__ bias, float* __restrict__ C,
                           int M, int N, int K, int ldc)
{
    __shared__ float As[128][36];
    __shared__ float Bs[32][132];
    __shared__ float biasS[16][128];

    const int tid = threadIdx.x;
    const int rowBase = blockIdx.y * 128;
    const int colBase = blockIdx.x * 128;
    const int warpId = tid >> 5;
    const int wm = (warpId >> 2) * 64;
    const int wn = (warpId & 3) * 32;

    for (int i = tid; i < 16 * 128; i += 256)
        biasS[i >> 7][i & 127] = bias[colBase + (i & 127)];
    __syncthreads();

    wmma::fragment<wmma::accumulator, 16, 16, 8, float> acc[4][2];
    {
        wmma::fragment<wmma::accumulator, 16, 16, 8, float> bfrag[2];
#pragma unroll
        for (int j = 0; j < 2; j++)
            wmma::load_matrix_sync(bfrag[j], &biasS[0][wn + j * 16], 128, wmma::mem_row_major);
#pragma unroll
        for (int i = 0; i < 4; i++)
#pragma unroll
            for (int j = 0; j < 2; j++) acc[i][j] = bfrag[j];
    }
    __syncthreads();

    const int ar = tid >> 3, ac4 = (tid & 7) * 4;
    const int br = tid >> 5, bc4 = (tid & 31) * 4;

    for (int kt = 0; kt < K; kt += 32) {
#pragma unroll
        for (int p = 0; p < 4; p++) {
            int row = p * 32 + ar;
            float4 v = *(const float4*)(A + (ll)(rowBase + row) * K + kt + ac4);
            As[row][ac4 + 0] = wmma::__float_to_tf32(v.x);
            As[row][ac4 + 1] = wmma::__float_to_tf32(v.y);
            As[row][ac4 + 2] = wmma::__float_to_tf32(v.z);
            As[row][ac4 + 3] = wmma::__float_to_tf32(v.w);
        }
#pragma unroll
        for (int p = 0; p < 4; p++) {
            int row = p * 8 + br;
            float4 v = *(const float4*)(B + (ll)(kt + row) * N + colBase + bc4);
            Bs[row][bc4 + 0] = wmma::__float_to_tf32(v.x);
            Bs[row][bc4 + 1] = wmma::__float_to_tf32(v.y);
            Bs[row][bc4 + 2] = wmma::__float_to_tf32(v.z);
            Bs[row][bc4 + 3] = wmma::__float_to_tf32(v.w);
        }
        __syncthreads();

#pragma unroll
        for (int ks = 0; ks < 32; ks += 8) {
            wmma::fragment<wmma::matrix_a, 16, 16, 8, wmma::precision::tf32, wmma::row_major> af[4];
            wmma::fragment<wmma::matrix_b, 16, 16, 8, wmma::precision::tf32, wmma::row_major> bf[2];
#pragma unroll
            for (int i = 0; i < 4; i++) wmma::load_matrix_sync(af[i], &As[wm + i * 16][ks], 36);
#pragma unroll
            for (int j = 0; j < 2; j++) wmma::load_matrix_sync(bf[j], &Bs[ks][wn + j * 16], 132);
#pragma unroll
            for (int i = 0; i < 4; i++)
#pragma unroll
                for (int j = 0; j < 2; j++) wmma::mma_sync(acc[i][j], af[i], bf[j], acc[i][j]);
        }
        __syncthreads();
    }

#pragma unroll
    for (int i = 0; i < 4; i++)
#pragma unroll
        for (int j = 0; j < 2; j++)
            wmma::store_matrix_sync(&C[(ll)(rowBase + wm + i * 16) * ldc + colBase + wn + j * 16],
                                    acc[i][j], ldc, wmma::mem_row_major);
}

// ================= generic register-blocked SGEMM (with lda/ldb) =================
template <int BM, int BN, int BK, int TM, int TN, bool TRANSB, bool RELU>
__global__ void sgemm_k(const float* __restrict__ A, const float* __restrict__ B,
                        const float* __restrict__ bias,
                        const float* __restrict__ accScale,
                        const float* __restrict__ biasScale,
                        float* __restrict__ C, int M, int N, int K,
                        int lda, int ldb, int ldc,
                        int rb, ll bStride, ll rOff)
{
    __shared__ float As[BK][BM];
    __shared__ float Bs[BK][BN];
    const int tid = threadIdx.x;
    const int rowBase = blockIdx.y * BM;
    const int colBase = blockIdx.x * BN;

    const int aRow = tid / (BK / 4);
    const int aCol = (tid % (BK / 4)) * 4;
    const int bRowNT = tid / (BK / 4);
    const int bColNT = (tid % (BK / 4)) * 4;
    const int bRowNN = tid / (BN / 4);
    const int bColNN = (tid % (BN / 4)) * 4;

    const int threadRow = tid / (BN / TN);
    const int threadCol = tid % (BN / TN);

    float acc[TM][TN];
#pragma unroll
    for (int i = 0; i < TM; i++)
#pragma unroll
        for (int j = 0; j < TN; j++) acc[i][j] = 0.f;

    for (int kt = 0; kt < K; kt += BK) {
        {
            int gr = rowBase + aRow;
            float4 av = make_float4(0.f, 0.f, 0.f, 0.f);
            if (gr < M) {
                const float* ap;
                if (rb > 0) ap = A + (ll)(gr / rb) * bStride + rOff + (ll)(gr % rb) * lda;
                else        ap = A + (ll)gr * lda;
                av = *(const float4*)(ap + kt + aCol);
            }
            As[aCol + 0][aRow] = av.x;
            As[aCol + 1][aRow] = av.y;
            As[aCol + 2][aRow] = av.z;
            As[aCol + 3][aRow] = av.w;
        }
        if (TRANSB) {
            float4 bv = *(const float4*)(B + (ll)(colBase + bRowNT) * ldb + kt + bColNT);
            Bs[bColNT + 0][bRowNT] = bv.x;
            Bs[bColNT + 1][bRowNT] = bv.y;
            Bs[bColNT + 2][bRowNT] = bv.z;
            Bs[bColNT + 3][bRowNT] = bv.w;
        } else {
            float4 bv = *(const float4*)(B + (ll)(kt + bRowNN) * ldb + colBase + bColNN);
            *(float4*)&Bs[bRowNN][bColNN] = bv;
        }
        __syncthreads();

#pragma unroll
        for (int kk = 0; kk < BK; kk++) {
            float ar[TM], br[TN];
#pragma unroll
            for (int i = 0; i < TM; i++) ar[i] = As[kk][threadRow * TM + i];
#pragma unroll
            for (int j = 0; j < TN; j++) br[j] = Bs[kk][threadCol * TN + j];
#pragma unroll
            for (int i = 0; i < TM; i++)
#pragma unroll
                for (int j = 0; j < TN; j++) acc[i][j] += ar[i] * br[j];
        }
        __syncthreads();
    }

    const float asc = accScale ? *accScale : 1.f;
    const float bsc = biasScale ? *biasScale : 1.f;
#pragma unroll
    for (int i = 0; i < TM; i++) {
        int r = rowBase + threadRow * TM + i;
        if (r >= M) continue;
#pragma unroll
        for (int j = 0; j < TN; j++) {
            int c = colBase + threadCol * TN + j;
            float v = asc * acc[i][j] + (bias ? bsc * bias[c] : 0.f);
            if (RELU) v = fmaxf(v, 0.f);
            C[(ll)r * ldc + c] = v;
        }
    }
}

// ---------------- small helpers ----------------
__global__ void pool_sums_k(const float* __restrict__ la_pool, const float* __restrict__ go_pool)
{
    int lane = threadIdx.x;
    float a = la_pool[lane];
    float b = go_pool[lane];
#pragma unroll
    for (int o = 16; o; o >>= 1) {
        a += __shfl_xor_sync(0xffffffffu, a, o);
        b += __shfl_xor_sync(0xffffffffu, b, o);
    }
    if (lane == 0) { g_scal[0] = a; g_scal[1] = b; }
}

// ======= fused GRU step =======
__global__ void gru_step_k(const float* __restrict__ wx, const float* __restrict__ Whh,
                           const float* __restrict__ b_hh,
                           const float* __restrict__ hin, float* __restrict__ hout,
                           float* __restrict__ qemb, int t)
{
    __shared__ float hs[32][68];
    __shared__ float ws[48][33];
    const int tid = threadIdx.x;
    const int j = blockIdx.x;
    const int tx = tid & 15;
    const int ty = tid >> 4;

    float accr[4] = {0, 0, 0, 0}, accz[4] = {0, 0, 0, 0}, accn[4] = {0, 0, 0, 0};
    const int hb = tid >> 3;
    const int hc4 = (tid & 7) * 4;

    for (int kt = 0; kt < D_; kt += 32) {
#pragma unroll
        for (int p = 0; p < 2; p++) {
            int bb = p * 32 + hb;
            float4 v = *(const float4*)(hin + (ll)bb * D_ + kt + hc4);
            hs[hc4 + 0][bb] = v.x;
            hs[hc4 + 1][bb] = v.y;
            hs[hc4 + 2][bb] = v.z;
            hs[hc4 + 3][bb] = v.w;
        }
        for (int idx = tid; idx < 384; idx += 256) {
            int r = idx >> 3, c4 = (idx & 7) * 4;
            int g = r >> 4, dd = r & 15;
            ll row = (ll)g * D_ + j * 16 + dd;
            float4 v = *(const float4*)(Whh + row * D_ + kt + c4);
            ws[r][c4 + 0] = v.x;
            ws[r][c4 + 1] = v.y;
            ws[r][c4 + 2] = v.z;
            ws[r][c4 + 3] = v.w;
        }
        __syncthreads();

#pragma unroll
        for (int kk = 0; kk < 32; kk++) {
            float wr = ws[tx][kk], wz = ws[16 + tx][kk], wn = ws[32 + tx][kk];
#pragma unroll
            for (int i = 0; i < 4; i++) {
                float hv = hs[kk][ty * 4 + i];
                accr[i] += hv * wr;
                accz[i] += hv * wz;
                accn[i] += hv * wn;
            }
        }
        __syncthreads();
    }

    const int d = j * 16 + tx;
    const float bhr = b_hh[d], bhz = b_hh[D_ + d], bhn = b_hh[2 * D_ + d];
#pragma unroll
    for (int i = 0; i < 4; i++) {
        int b = ty * 4 + i;
        ll o = (ll)b * 3 * D_;
        float xr = wx[o + d], xz = wx[o + D_ + d], xn = wx[o + 2 * D_ + d];
        float r = 1.f / (1.f + __expf(-(xr + accr[i] + bhr)));
        float z = 1.f / (1.f + __expf(-(xz + accz[i] + bhz)));
        float n = tanhf(xn + r * (accn[i] + bhn));
        float hv = (1.f - z) * n + z * hin[(ll)b * D_ + d];
        hout[(ll)b * D_ + d] = hv;
        qemb[(ll)b * T_ * D_ + (ll)t * D_ + d] = hv;
    }
}

// ======= qb[h][m] = Q[m, h*384 : +384] . la_b1[h*384 : +384] =======
__global__ void qb_k(const float* __restrict__ Q, const float* __restrict__ bk,
                     float* __restrict__ qb)
{
    int idx = blockIdx.x * 256 + threadIdx.x;   // grid 16 -> 4096
    int h = idx >> 11, m = idx & 2047;
    const float* qr = Q + (ll)m * D_ + h * DK_;
    const float* br = bk + h * DK_;
    float s = 0.f;
#pragma unroll 8
    for (int j = 0; j < DK_; j++) s += qr[j] * br[j];
    qb[idx] = s;
}

// ======= scores: S[bh][q][k] = scale * (Qt[h, b*32+q] . img[b,1+k] + qb) =======
// grid (8 n-tiles, 128 bh), block 256
__global__ void scores_k(const float* __restrict__ Qt, const float* __restrict__ img,
                         const float* __restrict__ qb, float* __restrict__ S)
{
    const int bh = blockIdx.y, b = bh >> 1, h = bh & 1;
    const int n0 = blockIdx.x * 128;
    __shared__ float As[32][33];
    __shared__ float Bs[32][136];

    const float* Arow = Qt + (ll)h * M_Q * D_ + (ll)(b * T_) * D_;
    const float* Brow = img + (ll)b * NTOK * D_ + D_ + (ll)n0 * D_;   // key n0
    const int tid = threadIdx.x;
    const int ar = tid >> 3, ac4 = (tid & 7) * 4;
    const int bn = tid >> 1, half = (tid & 1) * 16;
    const int tr = tid >> 5, tc = tid & 31;

    float acc[4][4] = {};

    for (int kt = 0; kt < D_; kt += 32) {
        {
            float4 v = *(const float4*)(Arow + (ll)ar * D_ + kt + ac4);
            As[ar][ac4 + 0] = v.x; As[ar][ac4 + 1] = v.y;
            As[ar][ac4 + 2] = v.z; As[ar][ac4 + 3] = v.w;
        }
        if (n0 + bn < NLOC) {
            const float* kr = Brow + (ll)bn * D_ + kt + half;
#pragma unroll
            for (int jj = 0; jj < 16; jj += 4) {
                float4 v = *(const float4*)(kr + jj);
                Bs[half + jj + 0][bn] = v.x;
                Bs[half + jj + 1][bn] = v.y;
                Bs[half + jj + 2][bn] = v.z;
                Bs[half + jj + 3][bn] = v.w;
            }
        } else {
#pragma unroll
            for (int jj = 0; jj < 16; jj++) Bs[half + jj][bn] = 0.f;
        }
        __syncthreads();

#pragma unroll
        for (int kk = 0; kk < 32; kk++) {
            float a[4];
#pragma unroll
            for (int i = 0; i < 4; i++) a[i] = As[tr * 4 + i][kk];
            float4 bb = *(const float4*)&Bs[kk][tc * 4];
#pragma unroll
            for (int i = 0; i < 4; i++) {
                acc[i][0] += a[i] * bb.x;
                acc[i][1] += a[i] * bb.y;
                acc[i][2] += a[i] * bb.z;
                acc[i][3] += a[i] * bb.w;
            }
        }
        __syncthreads();
    }

    const float scale = rsqrtf((float)DK_);
#pragma unroll
    for (int i = 0; i < 4; i++) {
        int q = tr * 4 + i;
        float qv = qb[h * M_Q + b * T_ + q];
        float* sr = S + (ll)bh * T_ * NLOC + (ll)q * NLOC;
#pragma unroll
        for (int jj = 0; jj < 4; jj++) {
            int n = n0 + tc * 4 + jj;
            if (n < NLOC) sr[n] = (acc[i][jj] + qv) * scale;
        }
    }
}

// ======= softmax over 900 keys, 32 rows per bh =======
__global__ void softmax_k(float* __restrict__ S)
{
    const int bh = blockIdx.x;
    float* base = S + (ll)bh * T_ * NLOC;
    const int lane = threadIdx.x & 31, wp = threadIdx.x >> 5;
    for (int q = wp; q < T_; q += 8) {
        float* row = base + (ll)q * NLOC;
        float mx = -1e30f;
        for (int k = lane; k < NLOC; k += 32) mx = fmaxf(mx, row[k]);
#pragma unroll
        for (int o = 16; o; o >>= 1) mx = fmaxf(mx, __shfl_xor_sync(0xffffffffu, mx, o));
        float sum = 0.f;
        for (int k = lane; k < NLOC; k += 32) { float e = __expf(row[k] - mx); row[k] = e; sum += e; }
#pragma unroll
        for (int o = 16; o; o >>= 1) sum += __shfl_xor_sync(0xffffffffu, sum, o);
        float inv = 1.f / sum;
        for (int k = lane; k < NLOC; k += 32) row[k] *= inv;
    }
}

// ======= pool attention weights over q: wk[bh][k] = sum_q la[q]*attn[q][k] =======
__global__ void poolattn_k(const float* __restrict__ S, const float* __restrict__ la,
                           float* __restrict__ wk)
{
    const int bh = blockIdx.x;
    __shared__ float sla[T_];
    if (threadIdx.x < T_) sla[threadIdx.x] = la[threadIdx.x];
    __syncthreads();
    const float* base = S + (ll)bh * T_ * NLOC;
    for (int k = threadIdx.x; k < NLOC; k += 256) {
        float s = 0.f;
#pragma unroll
        for (int q = 0; q < T_; q++) s += sla[q] * base[(ll)q * NLOC + k];
        wk[(ll)bh * NLOC + k] = s;
    }
}

// ======= pooled ctxi: pctxi[bh][d] = sum_k wk[k]*img[b,1+k,d] =======
__global__ void pctxi_k(const float* __restrict__ wk, const float* __restrict__ img,
                        float* __restrict__ pctxi)
{
    const int bh = blockIdx.x, b = bh >> 1;
    __shared__ float swk[NLOC];
    for (int k = threadIdx.x; k < NLOC; k += 256) swk[k] = wk[(ll)bh * NLOC + k];
    __syncthreads();
    const float* ib = img + (ll)b * NTOK * D_ + D_;
    const int d = threadIdx.x;
    float a0 = 0.f, a1 = 0.f, a2 = 0.f;
    for (int k = 0; k < NLOC; k++) {
        float w = swk[k];
        const float* r = ib + (ll)k * D_;
        a0 += w * r[d];
        a1 += w * r[d + 256];
        a2 += w * r[d + 512];
    }
    float* o = pctxi + (ll)bh * D_;
    o[d] = a0; o[d + 256] = a1; o[d + 512] = a2;
}

// ---------------- host-side launch wrappers ----------------
static inline void small_nn(const float* A, const float* B, const float* bias,
                            const float* asc, const float* bsc, float* C,
                            int M, int N, int K, int lda, int ldb, int ldc,
                            int rb, ll bStride, ll rOff, bool relu)
{
    dim3 grid(N / 64, (M + 63) / 64);
    if (relu)
        sgemm_k<64, 64, 16, 4, 4, false, true><<<grid, 256>>>(A, B, bias, asc, bsc, C, M, N, K, lda, ldb, ldc, rb, bStride, rOff);
    else
        sgemm_k<64, 64, 16, 4, 4, false, false><<<grid, 256>>>(A, B, bias, asc, bsc, C, M, N, K, lda, ldb, ldc, rb, bStride, rOff);
}
static inline void small_nt(const float* A, const float* B, const float* bias,
                            const float* asc, const float* bsc, float* C,
                            int M, int N, int K, int lda, int ldb, int ldc)
{
    dim3 grid(N / 64, (M + 63) / 64);
    sgemm_k<64, 64, 16, 4, 4, true, false><<<grid, 256>>>(A, B, bias, asc, bsc, C, M, N, K, lda, ldb, ldc, 0, 0, 0);
}

extern "C" void kernel_launch(void* const* d_in, const int* in_sizes, int n_in,
                              void* d_out, int out_size)
{
    (void)in_sizes; (void)n_in; (void)out_size;
    const float* img      = (const float*)d_in[1];
    const float* h0       = (const float*)d_in[2];
    const float* gru_w_ih = (const float*)d_in[3];
    const float* gru_w_hh = (const float*)d_in[4];
    const float* gru_b_ih = (const float*)d_in[5];
    const float* gru_b_hh = (const float*)d_in[6];
    const float* ga_w     = (const float*)d_in[7];
    const float* ga_b     = (const float*)d_in[8];
    const float* ga_pool  = (const float*)d_in[9];
    const float* la_w     = (const float*)d_in[10];
    const float* la_b     = (const float*)d_in[11];
    const float* la_pool  = (const float*)d_in[12];
    const float* go_w     = (const float*)d_in[13];
    const float* go_b     = (const float*)d_in[14];
    const float* go_pool  = (const float*)d_in[15];
    const float* f1_w     = (const float*)d_in[16];
    const float* f1_b     = (const float*)d_in[17];
    const float* f2_w     = (const float*)d_in[18];
    const float* f2_b     = (const float*)d_in[19];
    const float* f3_w     = (const float*)d_in[20];
    const float* f3_b     = (const float*)d_in[21];
    float* out = (float*)d_out;

    float *pt1, *pu, *pt2, *pwx, *ph, *ph2, *pqemb, *pQ, *pQt, *pqb, *pS, *pwk, *ppctxi,
          *ppool, *phcat, *px1, *px2, *pscal;
    cudaGetSymbolAddress((void**)&pt1, g_t1);
    cudaGetSymbolAddress((void**)&pu, g_u);
    cudaGetSymbolAddress((void**)&pt2, g_t2);
    cudaGetSymbolAddress((void**)&pwx, g_wx);
    cudaGetSymbolAddress((void**)&ph, g_h);
    cudaGetSymbolAddress((void**)&ph2, g_h2);
    cudaGetSymbolAddress((void**)&pqemb, g_qemb);
    cudaGetSymbolAddress((void**)&pQ, g_Q);
    cudaGetSymbolAddress((void**)&pQt, g_Qt);
    cudaGetSymbolAddress((void**)&pqb, g_qb);
    cudaGetSymbolAddress((void**)&pS, g_S);
    cudaGetSymbolAddress((void**)&pwk, g_wk);
    cudaGetSymbolAddress((void**)&ppctxi, g_pctxi);
    cudaGetSymbolAddress((void**)&ppool, g_pooled);
    cudaGetSymbolAddress((void**)&phcat, g_hcat);
    cudaGetSymbolAddress((void**)&px1, g_x1);
    cudaGetSymbolAddress((void**)&px2, g_x2);
    cudaGetSymbolAddress((void**)&pscal, g_scal);

    const ll W2 = (ll)D_ * D_;
    const ll BSTR = (ll)NTOK * D_;

    pool_sums_k<<<1, 32>>>(la_pool, go_pool);

    // ---- ga path (constant GRU input): wx = ga_pool0*(((cls@W2+b2)@W3+b3)@W_ih^T) + b_ih ----
    small_nn(img, ga_w + 2 * W2, ga_b + 2 * D_, nullptr, nullptr, pt1, BSZ, D_, D_, D_, D_, D_, 1, BSTR, 0, false);
    small_nn(pt1, ga_w + 3 * W2, ga_b + 3 * D_, nullptr, nullptr, pu, BSZ, D_, D_, D_, D_, D_, 0, 0, 0, false);
    small_nt(pu, gru_w_ih, gru_b_ih, ga_pool, nullptr, pwx, BSZ, 3 * D_, D_, D_, D_, 3 * D_);

    // ---- go path (constant): hcat[:,768:] = sum(go_pool) * ((cls@W2+b2)@W3+b3) ----
    small_nn(img, go_w + 2 * W2, go_b + 2 * D_, nullptr, nullptr, pt2, BSZ, D_, D_, D_, D_, D_, 1, BSTR, 0, false);
    small_nn(pt2, go_w + 3 * W2, go_b + 3 * D_, pscal + 1, pscal + 1, phcat + D_, BSZ, D_, D_, D_, D_, 2 * D_, 0, 0, 0, false);

    // ---- GRU: 32 fused steps, double-buffered h ----
    cudaMemcpyAsync(ph, h0, (size_t)BSZ * D_ * sizeof(float), cudaMemcpyDeviceToDevice);
    for (int t = 0; t < T_; t++) {
        const float* hin = (t & 1) ? ph2 : ph;
        float* hout      = (t & 1) ? ph  : ph2;
        gru_step_k<<<48, 256>>>(pwx, gru_w_hh, gru_b_hh, hin, hout, pqemb, t);
    }

    // ---- Q projection (tf32): Q = qemb @ Wq + bq   [2048, 768] ----
    {
        dim3 grid(D_ / 128, M_Q / 128);
        tf32gemm_k<<<grid, 256>>>(pqemb, la_w + 0 * W2, la_b + 0 * D_, pQ, M_Q, D_, D_, D_);
    }

    // ---- query-side K projection: Qt[h] = Q_h @ Wk_h^T   [2048, 768] per head ----
    for (int h = 0; h < 2; h++)
        small_nt(pQ + h * DK_, la_w + 1 * W2 + h * DK_, nullptr, nullptr, nullptr,
                 pQt + (ll)h * M_Q * D_, M_Q, D_, DK_, D_, D_, D_);
    qb_k<<<16, 256>>>(pQ, la_b + 1 * D_, pqb);

    // ---- scores + softmax + attention pooling ----
    {
        dim3 grid(8, BSZ * 2);
        scores_k<<<grid, 256>>>(pQt, img, pqb, pS);
    }
    softmax_k<<<BSZ * 2, 256>>>(pS);
    poolattn_k<<<BSZ * 2, 256>>>(pS, la_pool, pwk);
    pctxi_k<<<BSZ * 2, 256>>>(pwk, img, ppctxi);

    // ---- pooled V projection per head: pooled[:, h*384:+384] = pctxi_h @ Wv_h + sum(la)*bv_h ----
    for (int h = 0; h < 2; h++)
        small_nn(ppctxi + h * D_, la_w + 2 * W2 + h * DK_, la_b + 2 * D_ + h * DK_,
                 nullptr, pscal, ppool + h * DK_, BSZ, DK_, D_, 2 * D_, D_, D_, 0, 0, 0, false);

    // ---- output projection: hcat[:, :768] = pooled @ W3 + sum(la)*b3 ----
    small_nn(ppool, la_w + 3 * W2, la_b + 3 * D_, nullptr, pscal, phcat, BSZ, D_, D_, D_, D_, 2 * D_, 0, 0, 0, false);

    // ---- MLP head ----
    small_nn(phcat, f1_w, f1_b, nullptr, nullptr, px1, BSZ, 1024, 2 * D_, 2 * D_, 1024, 1024, 0, 0, 0, false);
    small_nn(px1, f2_w, f2_b, nullptr, nullptr, px2, BSZ, 512, 1024, 1024, 512, 512, 0, 0, 0, true);
    small_nn(px2, f3_w, f3_b, nullptr, nullptr, out, BSZ, 1024, 512, 512, 1024, 1024, 0, 0, 0, false);
}

// round 10
// speedup vs baseline: 8.1731x; 1.5690x over previous
#include <cuda_runtime.h>
#include <mma.h>
#include <math.h>

using namespace nvcuda;
typedef long long ll;

#define D_    768
#define BSZ   64
#define T_    32
#define NTOK  901
#define NLOC  900
#define DK_   384
#define M_Q   (BSZ * T_)   // 2048
#define GRU_BLOCKS 96

// ---------------- scratch (static device globals; no allocation) ----------------
__device__ float g_t1[BSZ * D_];
__device__ float g_u[BSZ * D_];
__device__ float g_t2[BSZ * D_];
__device__ float g_wx[BSZ * 3 * D_];
__device__ float g_h[BSZ * D_];
__device__ float g_h2[BSZ * D_];
__device__ float g_qemb[M_Q * D_];
__device__ float g_Q[M_Q * D_];
__device__ float g_Qt[2 * M_Q * D_];
__device__ float g_qb[2 * M_Q];
__device__ float g_S[(ll)BSZ * 2 * T_ * NLOC];
__device__ float g_wk[BSZ * 2 * NLOC];
__device__ float g_pctxi[BSZ * 2 * D_];
__device__ float g_pooled[BSZ * D_];
__device__ float g_hcat[BSZ * 2 * D_];
__device__ float g_x1[BSZ * 1024];
__device__ float g_x2[BSZ * 512];
__device__ float g_scal[2];
__device__ int   g_cnt;     // grid barrier counter (reset by pool_sums_k each launch)

// ================= TF32 tensor-core GEMM NN (Q projection) =================
__global__ void tf32gemm_k(const float* __restrict__ A, const float* __restrict__ B,
                           const float* __restrict__ bias, float* __restrict__ C,
                           int M, int N, int K, int ldc)
{
    __shared__ float As[128][36];
    __shared__ float Bs[32][132];
    __shared__ float biasS[16][128];

    const int tid = threadIdx.x;
    const int rowBase = blockIdx.y * 128;
    const int colBase = blockIdx.x * 128;
    const int warpId = tid >> 5;
    const int wm = (warpId >> 2) * 64;
    const int wn = (warpId & 3) * 32;

    for (int i = tid; i < 16 * 128; i += 256)
        biasS[i >> 7][i & 127] = bias[colBase + (i & 127)];
    __syncthreads();

    wmma::fragment<wmma::accumulator, 16, 16, 8, float> acc[4][2];
    {
        wmma::fragment<wmma::accumulator, 16, 16, 8, float> bfrag[2];
#pragma unroll
        for (int j = 0; j < 2; j++)
            wmma::load_matrix_sync(bfrag[j], &biasS[0][wn + j * 16], 128, wmma::mem_row_major);
#pragma unroll
        for (int i = 0; i < 4; i++)
#pragma unroll
            for (int j = 0; j < 2; j++) acc[i][j] = bfrag[j];
    }
    __syncthreads();

    const int ar = tid >> 3, ac4 = (tid & 7) * 4;
    const int br = tid >> 5, bc4 = (tid & 31) * 4;

    for (int kt = 0; kt < K; kt += 32) {
#pragma unroll
        for (int p = 0; p < 4; p++) {
            int row = p * 32 + ar;
            float4 v = *(const float4*)(A + (ll)(rowBase + row) * K + kt + ac4);
            As[row][ac4 + 0] = wmma::__float_to_tf32(v.x);
            As[row][ac4 + 1] = wmma::__float_to_tf32(v.y);
            As[row][ac4 + 2] = wmma::__float_to_tf32(v.z);
            As[row][ac4 + 3] = wmma::__float_to_tf32(v.w);
        }
#pragma unroll
        for (int p = 0; p < 4; p++) {
            int row = p * 8 + br;
            float4 v = *(const float4*)(B + (ll)(kt + row) * N + colBase + bc4);
            Bs[row][bc4 + 0] = wmma::__float_to_tf32(v.x);
            Bs[row][bc4 + 1] = wmma::__float_to_tf32(v.y);
            Bs[row][bc4 + 2] = wmma::__float_to_tf32(v.z);
            Bs[row][bc4 + 3] = wmma::__float_to_tf32(v.w);
        }
        __syncthreads();

#pragma unroll
        for (int ks = 0; ks < 32; ks += 8) {
            wmma::fragment<wmma::matrix_a, 16, 16, 8, wmma::precision::tf32, wmma::row_major> af[4];
            wmma::fragment<wmma::matrix_b, 16, 16, 8, wmma::precision::tf32, wmma::row_major> bf[2];
#pragma unroll
            for (int i = 0; i < 4; i++) wmma::load_matrix_sync(af[i], &As[wm + i * 16][ks], 36);
#pragma unroll
            for (int j = 0; j < 2; j++) wmma::load_matrix_sync(bf[j], &Bs[ks][wn + j * 16], 132);
#pragma unroll
            for (int i = 0; i < 4; i++)
#pragma unroll
                for (int j = 0; j < 2; j++) wmma::mma_sync(acc[i][j], af[i], bf[j], acc[i][j]);
        }
        __syncthreads();
    }

#pragma unroll
    for (int i = 0; i < 4; i++)
#pragma unroll
        for (int j = 0; j < 2; j++)
            wmma::store_matrix_sync(&C[(ll)(rowBase + wm + i * 16) * ldc + colBase + wn + j * 16],
                                    acc[i][j], ldc, wmma::mem_row_major);
}

// ================= TF32 NT GEMM: C[M,N] = A(M,K;lda) @ B(N,K;ldb)^T =================
// 64x64 tile per block, grid (N/64, M/64). K % 32 == 0.
__global__ void tc_nt_k(const float* __restrict__ A, const float* __restrict__ B,
                        float* __restrict__ C, int K, int lda, int ldb, int ldc)
{
    __shared__ float smem[2 * 64 * 36];
    float* As = smem;            // [64][36] (m,k)
    float* Bs = smem + 64 * 36;  // [64][36] (n,k)
    const int rowBase = blockIdx.y * 64;
    const int colBase = blockIdx.x * 64;
    const int tid = threadIdx.x;
    const int warp = tid >> 5;
    const int wm = (warp >> 2) * 32;
    const int wn = (warp & 3) * 16;

    wmma::fragment<wmma::accumulator, 16, 16, 8, float> acc[2];
    wmma::fill_fragment(acc[0], 0.f);
    wmma::fill_fragment(acc[1], 0.f);

    const int r = tid >> 3, k4 = (tid & 7) * 4;

    for (int kt = 0; kt < K; kt += 32) {
#pragma unroll
        for (int p = 0; p < 2; p++) {
            int m = p * 32 + r;
            float4 v = *(const float4*)(A + (ll)(rowBase + m) * lda + kt + k4);
            float* d = As + m * 36 + k4;
            d[0] = wmma::__float_to_tf32(v.x); d[1] = wmma::__float_to_tf32(v.y);
            d[2] = wmma::__float_to_tf32(v.z); d[3] = wmma::__float_to_tf32(v.w);
        }
#pragma unroll
        for (int p = 0; p < 2; p++) {
            int n = p * 32 + r;
            float4 v = *(const float4*)(B + (ll)(colBase + n) * ldb + kt + k4);
            float* d = Bs + n * 36 + k4;
            d[0] = wmma::__float_to_tf32(v.x); d[1] = wmma::__float_to_tf32(v.y);
            d[2] = wmma::__float_to_tf32(v.z); d[3] = wmma::__float_to_tf32(v.w);
        }
        __syncthreads();
#pragma unroll
        for (int ks = 0; ks < 32; ks += 8) {
            wmma::fragment<wmma::matrix_a, 16, 16, 8, wmma::precision::tf32, wmma::row_major> af[2];
            wmma::fragment<wmma::matrix_b, 16, 16, 8, wmma::precision::tf32, wmma::col_major> bf;
            wmma::load_matrix_sync(af[0], As + (wm + 0) * 36 + ks, 36);
            wmma::load_matrix_sync(af[1], As + (wm + 16) * 36 + ks, 36);
            wmma::load_matrix_sync(bf, Bs + wn * 36 + ks, 36);
            wmma::mma_sync(acc[0], af[0], bf, acc[0]);
            wmma::mma_sync(acc[1], af[1], bf, acc[1]);
        }
        __syncthreads();
    }
    wmma::store_matrix_sync(&C[(ll)(rowBase + wm + 0) * ldc + colBase + wn], acc[0], ldc, wmma::mem_row_major);
    wmma::store_matrix_sync(&C[(ll)(rowBase + wm + 16) * ldc + colBase + wn], acc[1], ldc, wmma::mem_row_major);
}

// ================= TF32 scores: S[bh][q][n] = (Qt_h[bq] . img_key[n] + qb)*scale ======
// grid (15 n-tiles of 64, 64 batches), block 256. M=64 (2 heads x 32 q).
__global__ void scores_tc_k(const float* __restrict__ Qt, const float* __restrict__ img,
                            const float* __restrict__ qb, float* __restrict__ S)
{
    __shared__ float smem[2 * 64 * 36];
    float* As = smem;
    float* Bs = smem + 64 * 36;
    const int b = blockIdx.y;
    const int n0 = blockIdx.x * 64;
    const int tid = threadIdx.x;
    const int warp = tid >> 5;
    const int wm = (warp >> 2) * 32;
    const int wn = (warp & 3) * 16;

    wmma::fragment<wmma::accumulator, 16, 16, 8, float> acc[2];
    wmma::fill_fragment(acc[0], 0.f);
    wmma::fill_fragment(acc[1], 0.f);

    const int r = tid >> 3, k4 = (tid & 7) * 4;
    const float* imgb = img + (ll)b * NTOK * D_ + D_;   // first local key

    for (int kt = 0; kt < D_; kt += 32) {
#pragma unroll
        for (int p = 0; p < 2; p++) {
            int m = p * 32 + r;
            int h = m >> 5, q = m & 31;
            float4 v = *(const float4*)(Qt + (ll)h * M_Q * D_ + ((ll)b * T_ + q) * D_ + kt + k4);
            float* d = As + m * 36 + k4;
            d[0] = wmma::__float_to_tf32(v.x); d[1] = wmma::__float_to_tf32(v.y);
            d[2] = wmma::__float_to_tf32(v.z); d[3] = wmma::__float_to_tf32(v.w);
        }
#pragma unroll
        for (int p = 0; p < 2; p++) {
            int n = p * 32 + r;
            float4 v = make_float4(0.f, 0.f, 0.f, 0.f);
            if (n0 + n < NLOC)
                v = *(const float4*)(imgb + (ll)(n0 + n) * D_ + kt + k4);
            float* d = Bs + n * 36 + k4;
            d[0] = wmma::__float_to_tf32(v.x); d[1] = wmma::__float_to_tf32(v.y);
            d[2] = wmma::__float_to_tf32(v.z); d[3] = wmma::__float_to_tf32(v.w);
        }
        __syncthreads();
#pragma unroll
        for (int ks = 0; ks < 32; ks += 8) {
            wmma::fragment<wmma::matrix_a, 16, 16, 8, wmma::precision::tf32, wmma::row_major> af[2];
            wmma::fragment<wmma::matrix_b, 16, 16, 8, wmma::precision::tf32, wmma::col_major> bf;
            wmma::load_matrix_sync(af[0], As + (wm + 0) * 36 + ks, 36);
            wmma::load_matrix_sync(af[1], As + (wm + 16) * 36 + ks, 36);
            wmma::load_matrix_sync(bf, Bs + wn * 36 + ks, 36);
            wmma::mma_sync(acc[0], af[0], bf, acc[0]);
            wmma::mma_sync(acc[1], af[1], bf, acc[1]);
        }
        __syncthreads();
    }
    // stage C into smem (aliases As/Bs; safe: everyone only writes now)
    float* Cs = smem;  // [64][64]
    wmma::store_matrix_sync(Cs + (wm + 0) * 64 + wn, acc[0], 64, wmma::mem_row_major);
    wmma::store_matrix_sync(Cs + (wm + 16) * 64 + wn, acc[1], 64, wmma::mem_row_major);
    __syncthreads();
    const float scale = rsqrtf((float)DK_);
    for (int idx = tid; idx < 64 * 64; idx += 256) {
        int m = idx >> 6, n = idx & 63;
        if (n0 + n < NLOC) {
            int h = m >> 5, q = m & 31;
            S[((ll)(b * 2 + h) * T_ + q) * NLOC + n0 + n] =
                (Cs[idx] + qb[h * M_Q + b * T_ + q]) * scale;
        }
    }
}

// ================= skinny GEMM: M=64, 16-col tile per block =================
// C[64,N] = asc*(A@B(^T)) + bsc*bias. grid = N/16, block 256. K%32==0.
// rb==1: A row m -> A + m*bStride (gathered cls rows); else A + m*lda.
template <bool TRANSB, bool RELU>
__global__ void skinny_k(const float* __restrict__ A, const float* __restrict__ B,
                         const float* __restrict__ bias,
                         const float* __restrict__ accScale,
                         const float* __restrict__ biasScale,
                         float* __restrict__ C, int K,
                         int lda, int ldb, int ldc, int rb, ll bStride)
{
    __shared__ float As[32][68];   // [k][m]
    __shared__ float Bs[32][17];   // [k][n]
    const int tid = threadIdx.x;
    const int colBase = blockIdx.x * 16;
    const int c = tid & 15, r4 = tid >> 4;
    float acc[4] = {0.f, 0.f, 0.f, 0.f};
    const int am = tid >> 3, ak4 = (tid & 7) * 4;

    for (int kt = 0; kt < K; kt += 32) {
#pragma unroll
        for (int p = 0; p < 2; p++) {
            int gm = p * 32 + am;
            const float* ap = (rb > 0) ? A + (ll)gm * bStride : A + (ll)gm * lda;
            float4 v = *(const float4*)(ap + kt + ak4);
            As[ak4 + 0][gm] = v.x; As[ak4 + 1][gm] = v.y;
            As[ak4 + 2][gm] = v.z; As[ak4 + 3][gm] = v.w;
        }
        if (tid < 128) {
            if (TRANSB) {
                int n = tid >> 3, k4 = (tid & 7) * 4;
                float4 v = *(const float4*)(B + (ll)(colBase + n) * ldb + kt + k4);
                Bs[k4 + 0][n] = v.x; Bs[k4 + 1][n] = v.y;
                Bs[k4 + 2][n] = v.z; Bs[k4 + 3][n] = v.w;
            } else {
                int k = tid >> 2, c4 = (tid & 3) * 4;
                float4 v = *(const float4*)(B + (ll)(kt + k) * ldb + colBase + c4);
                Bs[k][c4 + 0] = v.x; Bs[k][c4 + 1] = v.y;
                Bs[k][c4 + 2] = v.z; Bs[k][c4 + 3] = v.w;
            }
        }
        __syncthreads();
#pragma unroll
        for (int kk = 0; kk < 32; kk++) {
            float bv = Bs[kk][c];
            float4 a = *(const float4*)&As[kk][r4 * 4];
            acc[0] += a.x * bv; acc[1] += a.y * bv;
            acc[2] += a.z * bv; acc[3] += a.w * bv;
        }
        __syncthreads();
    }
    const float asc = accScale ? *accScale : 1.f;
    const float bb = bias ? (biasScale ? *biasScale : 1.f) * bias[colBase + c] : 0.f;
#pragma unroll
    for (int i = 0; i < 4; i++) {
        float v = asc * acc[i] + bb;
        if (RELU) v = fmaxf(v, 0.f);
        C[(ll)(r4 * 4 + i) * ldc + colBase + c] = v;
    }
}

// ---------------- small helpers ----------------
__global__ void pool_sums_k(const float* __restrict__ la_pool, const float* __restrict__ go_pool)
{
    int lane = threadIdx.x;
    float a = la_pool[lane];
    float b = go_pool[lane];
#pragma unroll
    for (int o = 16; o; o >>= 1) {
        a += __shfl_xor_sync(0xffffffffu, a, o);
        b += __shfl_xor_sync(0xffffffffu, b, o);
    }
    if (lane == 0) { g_scal[0] = a; g_scal[1] = b; g_cnt = 0; }
}

// ======= persistent GRU: 96 blocks = 48 d-slices x 2 batch halves, Whh in smem =======
__global__ void gru_persist_k(const float* __restrict__ wx, const float* __restrict__ Whh,
                              const float* __restrict__ b_hh,
                              float* __restrict__ hA, float* __restrict__ hB,
                              float* __restrict__ qemb)
{
    extern __shared__ float sm[];
    float* ws = sm;                 // [48][769]
    float* hs = sm + 48 * 769;      // [32][36]
    const int tid = threadIdx.x;    // 256
    const int j  = blockIdx.x >> 1;
    const int b0 = (blockIdx.x & 1) * 32;
    const int tx = tid & 15;
    const int ty = tid >> 4;        // 16 groups of 2 batches

    // load Whh slice once: 48 rows (3 gates x 16 d) x 768
    for (int idx = tid; idx < 48 * 192; idx += 256) {
        int rr = idx / 192, c4 = (idx - rr * 192) * 4;
        int g = rr >> 4, dd = rr & 15;
        float4 v = *(const float4*)(Whh + ((ll)g * D_ + j * 16 + dd) * D_ + c4);
        float* w = ws + rr * 769 + c4;
        w[0] = v.x; w[1] = v.y; w[2] = v.z; w[3] = v.w;
    }
    const int d = j * 16 + tx;
    float wxr[2], wxz[2], wxn[2];
#pragma unroll
    for (int i = 0; i < 2; i++) {
        ll o = (ll)(b0 + ty * 2 + i) * (3 * D_);
        wxr[i] = wx[o + d]; wxz[i] = wx[o + D_ + d]; wxn[i] = wx[o + 2 * D_ + d];
    }
    const float bhr = b_hh[d], bhz = b_hh[D_ + d], bhn = b_hh[2 * D_ + d];
    __syncthreads();

    const int hm = tid >> 3;          // batch-within-half for staging
    const int hk4 = (tid & 7) * 4;

    for (int t = 0; t < T_; t++) {
        const float* hin = (t & 1) ? hB : hA;
        float* hout      = (t & 1) ? hA : hB;
        float ar0 = 0.f, ar1 = 0.f, az0 = 0.f, az1 = 0.f, an0 = 0.f, an1 = 0.f;
        for (int kt = 0; kt < D_; kt += 32) {
            float4 v = __ldcg((const float4*)(hin + (ll)(b0 + hm) * D_ + kt + hk4));
            hs[(hk4 + 0) * 36 + hm] = v.x; hs[(hk4 + 1) * 36 + hm] = v.y;
            hs[(hk4 + 2) * 36 + hm] = v.z; hs[(hk4 + 3) * 36 + hm] = v.w;
            __syncthreads();
            const float* w0 = ws + tx * 769 + kt;
            const float* w1 = w0 + 16 * 769;
            const float* w2 = w0 + 32 * 769;
            const float* hp = hs + ty * 2;
#pragma unroll
            for (int kk = 0; kk < 32; kk++) {
                float h0v = hp[kk * 36], h1v = hp[kk * 36 + 1];
                float wr = w0[kk], wz = w1[kk], wn = w2[kk];
                ar0 += h0v * wr; ar1 += h1v * wr;
                az0 += h0v * wz; az1 += h1v * wz;
                an0 += h0v * wn; an1 += h1v * wn;
            }
            __syncthreads();
        }
        {
            int b = b0 + ty * 2;
            float hp0 = __ldcg(hin + (ll)b * D_ + d);
            float hp1 = __ldcg(hin + (ll)(b + 1) * D_ + d);
            float r0 = 1.f / (1.f + __expf(-(wxr[0] + ar0 + bhr)));
            float z0 = 1.f / (1.f + __expf(-(wxz[0] + az0 + bhz)));
            float n0 = tanhf(wxn[0] + r0 * (an0 + bhn));
            float h0n = (1.f - z0) * n0 + z0 * hp0;
            float r1 = 1.f / (1.f + __expf(-(wxr[1] + ar1 + bhr)));
            float z1 = 1.f / (1.f + __expf(-(wxz[1] + az1 + bhz)));
            float n1 = tanhf(wxn[1] + r1 * (an1 + bhn));
            float h1n = (1.f - z1) * n1 + z1 * hp1;
            __stcg(hout + (ll)b * D_ + d, h0n);
            __stcg(hout + (ll)(b + 1) * D_ + d, h1n);
            qemb[((ll)b * T_ + t) * D_ + d] = h0n;
            qemb[((ll)(b + 1) * T_ + t) * D_ + d] = h1n;
        }
        if (t < T_ - 1) {
            __syncthreads();
            if (tid == 0) {
                __threadfence();
                atomicAdd(&g_cnt, 1);
                const int target = GRU_BLOCKS * (t + 1);
                while (atomicAdd(&g_cnt, 0) < target) {}
            }
            __syncthreads();
        }
    }
}

// ======= qb[h][m] = Q[m, h*384:+384] . bk[h*384:+384] =======
__global__ void qb_k(const float* __restrict__ Q, const float* __restrict__ bk,
                     float* __restrict__ qb)
{
    int idx = blockIdx.x * 256 + threadIdx.x;
    int h = idx >> 11, m = idx & 2047;
    const float* qr = Q + (ll)m * D_ + h * DK_;
    const float* br = bk + h * DK_;
    float s = 0.f;
#pragma unroll 8
    for (int j = 0; j < DK_; j++) s += qr[j] * br[j];
    qb[idx] = s;
}

// ======= fused softmax + la-pool: wk[bh][k] = sum_q la[q]*softmax(S[bh][q])[k] =======
__global__ void spool_k(const float* __restrict__ S, const float* __restrict__ la,
                        float* __restrict__ wk)
{
    extern __shared__ float sS[];   // [32][901]
    __shared__ float sla[T_];
    const int bh = blockIdx.x;
    const int tid = threadIdx.x;
    if (tid < T_) sla[tid] = la[tid];
    __syncthreads();
    const float* base = S + (ll)bh * T_ * NLOC;
    const int lane = tid & 31, wp = tid >> 5;
    for (int q = wp; q < T_; q += 8) {
        const float* row = base + (ll)q * NLOC;
        float* srow = sS + q * 901;
        float mx = -1e30f;
        for (int k = lane; k < NLOC; k += 32) { float v = row[k]; srow[k] = v; mx = fmaxf(mx, v); }
#pragma unroll
        for (int o = 16; o; o >>= 1) mx = fmaxf(mx, __shfl_xor_sync(0xffffffffu, mx, o));
        float sum = 0.f;
        for (int k = lane; k < NLOC; k += 32) { float e = __expf(srow[k] - mx); srow[k] = e; sum += e; }
#pragma unroll
        for (int o = 16; o; o >>= 1) sum += __shfl_xor_sync(0xffffffffu, sum, o);
        float inv = sla[q] / sum;
        for (int k = lane; k < NLOC; k += 32) srow[k] *= inv;
    }
    __syncthreads();
    for (int k = tid; k < NLOC; k += 256) {
        float s = 0.f;
#pragma unroll
        for (int q = 0; q < T_; q++) s += sS[q * 901 + k];
        wk[(ll)bh * NLOC + k] = s;
    }
}

// ======= pctxi[bh][d] = sum_k wk[bh][k]*img[b,1+k,d]  (both heads, one img pass) =======
__global__ void pctxi2_k(const float* __restrict__ wk, const float* __restrict__ img,
                         float* __restrict__ pctxi)
{
    __shared__ float swk[2][NLOC];
    const int b = blockIdx.x;
    const int tid = threadIdx.x;   // 256
    for (int k = tid; k < 2 * NLOC; k += 256)
        swk[k / NLOC][k % NLOC] = wk[(ll)(b * 2) * NLOC + k];
    __syncthreads();
    const float* ib = img + (ll)b * NTOK * D_ + D_;
    const int d = tid;
    float a00 = 0.f, a01 = 0.f, a02 = 0.f, a10 = 0.f, a11 = 0.f, a12 = 0.f;
    for (int k = 0; k < NLOC; k++) {
        const float* r = ib + (ll)k * D_;
        float w0 = swk[0][k], w1 = swk[1][k];
        float v0 = r[d], v1 = r[d + 256], v2 = r[d + 512];
        a00 += w0 * v0; a01 += w0 * v1; a02 += w0 * v2;
        a10 += w1 * v0; a11 += w1 * v1; a12 += w1 * v2;
    }
    float* o0 = pctxi + (ll)(b * 2) * D_;
    float* o1 = o0 + D_;
    o0[d] = a00; o0[d + 256] = a01; o0[d + 512] = a02;
    o1[d] = a10; o1[d + 256] = a11; o1[d + 512] = a12;
}

// ---------------- host-side launch wrappers ----------------
static inline void skinny(const float* A, const float* B, const float* bias,
                          const float* asc, const float* bsc, float* C,
                          int N, int K, int lda, int ldb, int ldc,
                          int rb, ll bStride, bool transb, bool relu)
{
    dim3 grid(N / 16);
    if (transb)
        skinny_k<true, false><<<grid, 256>>>(A, B, bias, asc, bsc, C, K, lda, ldb, ldc, rb, bStride);
    else if (relu)
        skinny_k<false, true><<<grid, 256>>>(A, B, bias, asc, bsc, C, K, lda, ldb, ldc, rb, bStride);
    else
        skinny_k<false, false><<<grid, 256>>>(A, B, bias, asc, bsc, C, K, lda, ldb, ldc, rb, bStride);
}

extern "C" void kernel_launch(void* const* d_in, const int* in_sizes, int n_in,
                              void* d_out, int out_size)
{
    (void)in_sizes; (void)n_in; (void)out_size;
    const float* img      = (const float*)d_in[1];
    const float* h0       = (const float*)d_in[2];
    const float* gru_w_ih = (const float*)d_in[3];
    const float* gru_w_hh = (const float*)d_in[4];
    const float* gru_b_ih = (const float*)d_in[5];
    const float* gru_b_hh = (const float*)d_in[6];
    const float* ga_w     = (const float*)d_in[7];
    const float* ga_b     = (const float*)d_in[8];
    const float* ga_pool  = (const float*)d_in[9];
    const float* la_w     = (const float*)d_in[10];
    const float* la_b     = (const float*)d_in[11];
    const float* la_pool  = (const float*)d_in[12];
    const float* go_w     = (const float*)d_in[13];
    const float* go_b     = (const float*)d_in[14];
    const float* go_pool  = (const float*)d_in[15];
    const float* f1_w     = (const float*)d_in[16];
    const float* f1_b     = (const float*)d_in[17];
    const float* f2_w     = (const float*)d_in[18];
    const float* f2_b     = (const float*)d_in[19];
    const float* f3_w     = (const float*)d_in[20];
    const float* f3_b     = (const float*)d_in[21];
    float* out = (float*)d_out;

    float *pt1, *pu, *pt2, *pwx, *ph, *ph2, *pqemb, *pQ, *pQt, *pqb, *pS, *pwk, *ppctxi,
          *ppool, *phcat, *px1, *px2, *pscal;
    cudaGetSymbolAddress((void**)&pt1, g_t1);
    cudaGetSymbolAddress((void**)&pu, g_u);
    cudaGetSymbolAddress((void**)&pt2, g_t2);
    cudaGetSymbolAddress((void**)&pwx, g_wx);
    cudaGetSymbolAddress((void**)&ph, g_h);
    cudaGetSymbolAddress((void**)&ph2, g_h2);
    cudaGetSymbolAddress((void**)&pqemb, g_qemb);
    cudaGetSymbolAddress((void**)&pQ, g_Q);
    cudaGetSymbolAddress((void**)&pQt, g_Qt);
    cudaGetSymbolAddress((void**)&pqb, g_qb);
    cudaGetSymbolAddress((void**)&pS, g_S);
    cudaGetSymbolAddress((void**)&pwk, g_wk);
    cudaGetSymbolAddress((void**)&ppctxi, g_pctxi);
    cudaGetSymbolAddress((void**)&ppool, g_pooled);
    cudaGetSymbolAddress((void**)&phcat, g_hcat);
    cudaGetSymbolAddress((void**)&px1, g_x1);
    cudaGetSymbolAddress((void**)&px2, g_x2);
    cudaGetSymbolAddress((void**)&pscal, g_scal);

    const ll W2 = (ll)D_ * D_;
    const ll BSTR = (ll)NTOK * D_;

    // smem opt-in attributes (idempotent)
    const int gru_smem = (48 * 769 + 32 * 36) * 4;       // 152,256
    const int spool_smem = 32 * 901 * 4;                 // 115,328
    cudaFuncSetAttribute(gru_persist_k, cudaFuncAttributeMaxDynamicSharedMemorySize, gru_smem);
    cudaFuncSetAttribute(spool_k, cudaFuncAttributeMaxDynamicSharedMemorySize, spool_smem);

    pool_sums_k<<<1, 32>>>(la_pool, go_pool);   // also resets grid-barrier counter

    // ---- ga path (constant GRU input): wx = ga_pool0*(((cls@W2+b2)@W3+b3)@W_ih^T) + b_ih ----
    skinny(img, ga_w + 2 * W2, ga_b + 2 * D_, nullptr, nullptr, pt1, D_, D_, D_, D_, D_, 1, BSTR, false, false);
    skinny(pt1, ga_w + 3 * W2, ga_b + 3 * D_, nullptr, nullptr, pu, D_, D_, D_, D_, D_, 0, 0, false, false);
    skinny(pu, gru_w_ih, gru_b_ih, ga_pool, nullptr, pwx, 3 * D_, D_, D_, D_, 3 * D_, 0, 0, true, false);

    // ---- go path (constant): hcat[:,768:] = sum(go_pool) * ((cls@W2+b2)@W3+b3) ----
    skinny(img, go_w + 2 * W2, go_b + 2 * D_, nullptr, nullptr, pt2, D_, D_, D_, D_, D_, 1, BSTR, false, false);
    skinny(pt2, go_w + 3 * W2, go_b + 3 * D_, pscal + 1, pscal + 1, phcat + D_, D_, D_, D_, D_, 2 * D_, 0, 0, false, false);

    // ---- GRU: persistent kernel, 32 steps with internal grid barrier ----
    cudaMemcpyAsync(ph, h0, (size_t)BSZ * D_ * sizeof(float), cudaMemcpyDeviceToDevice);
    gru_persist_k<<<GRU_BLOCKS, 256, gru_smem>>>(pwx, gru_w_hh, gru_b_hh, ph, ph2, pqemb);

    // ---- Q projection (tf32 NN): Q = qemb @ Wq + bq ----
    {
        dim3 grid(D_ / 128, M_Q / 128);
        tf32gemm_k<<<grid, 256>>>(pqemb, la_w + 0 * W2, la_b + 0 * D_, pQ, M_Q, D_, D_, D_);
    }

    // ---- query-side K projection (tf32 NT): Qt[h] = Q_h @ Wk_h^T ----
    for (int h = 0; h < 2; h++) {
        dim3 grid(D_ / 64, M_Q / 64);
        tc_nt_k<<<grid, 256>>>(pQ + h * DK_, la_w + 1 * W2 + h * DK_,
                               pQt + (ll)h * M_Q * D_, DK_, D_, D_, D_);
    }
    qb_k<<<16, 256>>>(pQ, la_b + 1 * D_, pqb);

    // ---- scores (tf32) + fused softmax/pool + pooled ctx ----
    {
        dim3 grid((NLOC + 63) / 64, BSZ);
        scores_tc_k<<<grid, 256>>>(pQt, img, pqb, pS);
    }
    spool_k<<<BSZ * 2, 256, spool_smem>>>(pS, la_pool, pwk);
    pctxi2_k<<<BSZ, 256>>>(pwk, img, ppctxi);

    // ---- pooled V projection per head + output projection ----
    for (int h = 0; h < 2; h++)
        skinny(ppctxi + h * D_, la_w + 2 * W2 + h * DK_, la_b + 2 * D_ + h * DK_,
               nullptr, pscal, ppool + h * DK_, DK_, D_, 2 * D_, D_, D_, 0, 0, false, false);
    skinny(ppool, la_w + 3 * W2, la_b + 3 * D_, nullptr, pscal, phcat, D_, D_, D_, D_, 2 * D_, 0, 0, false, false);

    // ---- MLP head ----
    skinny(phcat, f1_w, f1_b, nullptr, nullptr, px1, 1024, 2 * D_, 2 * D_, 1024, 1024, 0, 0, false, false);
    skinny(px1, f2_w, f2_b, nullptr, nullptr, px2, 512, 1024, 1024, 512, 512, 0, 0, false, true);
    skinny(px2, f3_w, f3_b, nullptr, nullptr, out, 1024, 512, 512, 1024, 1024, 0, 0, false, false);
}